// round 1
// baseline (speedup 1.0000x reference)
#include <cuda_runtime.h>

#define EMBED    1024
#define HEADS    16
#define HEAD_DIM 64
#define SEQ      2048
#define BATCH    2
#define QKSCALE  0.125f   // HEAD_DIM^-0.5

// Scratch (allocation-free): QKV output and attention output
__device__ float g_qkv[(size_t)BATCH * SEQ * 3 * EMBED];   // [B*N, 3*E]
__device__ float g_att[(size_t)BATCH * SEQ * EMBED];       // [B*N, E]

// ---------------------------------------------------------------------------
// SGEMM "NT": C[m,n] = sum_k A[m,k] * W[n,k] + bias[n]
// A row-major [M,K], W row-major [N,K] (both K-contiguous). M,N,K multiples
// of tile sizes. 128x128x8 tile, 256 threads, 8x8 micro-tile per thread.
// ---------------------------------------------------------------------------
template<int BM, int BN, int BK>
__global__ __launch_bounds__(256)
void sgemm_nt_bias(const float* __restrict__ A,
                   const float* __restrict__ W,
                   const float* __restrict__ bias,
                   float* __restrict__ C,
                   int M, int N, int K)
{
    __shared__ float As[BK][BM + 4];
    __shared__ float Ws[BK][BN + 4];

    const int t  = threadIdx.x;
    const int tx = t & 15;
    const int ty = t >> 4;
    const int row0 = blockIdx.y * BM;
    const int col0 = blockIdx.x * BN;

    // loader: each thread fetches one float4 of A and one of W per k-step
    const int lr = t >> 1;          // 0..127
    const int lk = (t & 1) * 4;     // 0 or 4
    const float* Ap = A + (size_t)(row0 + lr) * K + lk;
    const float* Wp = W + (size_t)(col0 + lr) * K + lk;

    float acc[8][8] = {};

    for (int kt = 0; kt < K; kt += BK) {
        float4 av = *(const float4*)(Ap + kt);
        float4 wv = *(const float4*)(Wp + kt);
        __syncthreads();
        As[lk + 0][lr] = av.x; As[lk + 1][lr] = av.y;
        As[lk + 2][lr] = av.z; As[lk + 3][lr] = av.w;
        Ws[lk + 0][lr] = wv.x; Ws[lk + 1][lr] = wv.y;
        Ws[lk + 2][lr] = wv.z; Ws[lk + 3][lr] = wv.w;
        __syncthreads();

        #pragma unroll
        for (int kk = 0; kk < BK; kk++) {
            float4 a0 = *(const float4*)&As[kk][ty * 8];
            float4 a1 = *(const float4*)&As[kk][ty * 8 + 4];
            float4 b0 = *(const float4*)&Ws[kk][tx * 8];
            float4 b1 = *(const float4*)&Ws[kk][tx * 8 + 4];
            float af[8] = {a0.x, a0.y, a0.z, a0.w, a1.x, a1.y, a1.z, a1.w};
            float bf[8] = {b0.x, b0.y, b0.z, b0.w, b1.x, b1.y, b1.z, b1.w};
            #pragma unroll
            for (int i = 0; i < 8; i++)
                #pragma unroll
                for (int j = 0; j < 8; j++)
                    acc[i][j] += af[i] * bf[j];
        }
    }

    #pragma unroll
    for (int i = 0; i < 8; i++) {
        const int r = row0 + ty * 8 + i;
        #pragma unroll
        for (int j = 0; j < 8; j += 4) {
            const int c = col0 + tx * 8 + j;
            float4 v;
            v.x = acc[i][j + 0] + bias[c + 0];
            v.y = acc[i][j + 1] + bias[c + 1];
            v.z = acc[i][j + 2] + bias[c + 2];
            v.w = acc[i][j + 3] + bias[c + 3];
            *(float4*)&C[(size_t)r * N + c] = v;
        }
    }
}

// ---------------------------------------------------------------------------
// Fused attention: per (b, h, q-tile of 64 rows), flash-style online softmax.
// Smem: Qt[64][68] (Q transposed), KPt[64][68] (K transposed, reused for P^T),
//       Vs[64][64] (V natural). 256 threads as 16x16; 4x4 micro-tiles.
// ---------------------------------------------------------------------------
__global__ __launch_bounds__(256)
void attn_kernel(const float* __restrict__ qkv, float* __restrict__ out)
{
    extern __shared__ float sm[];
    float* Qt  = sm;                 // [64][68]
    float* KPt = sm + 64 * 68;       // [64][68]
    float* Vs  = sm + 2 * 64 * 68;   // [64][64]

    const int t  = threadIdx.x;
    const int tx = t & 15;
    const int ty = t >> 4;
    const int qt = blockIdx.x;       // 0..31
    const int h  = blockIdx.y;       // 0..15
    const int b  = blockIdx.z;       // 0..1

    const size_t rowstride = 3 * EMBED;
    const float* qb = qkv + (size_t)b * SEQ * rowstride + (size_t)h * HEAD_DIM;
    const float* kb = qb + EMBED;
    const float* vb = qb + 2 * EMBED;
    const int q0 = qt * 64;

    // Load Q tile transposed: Qt[d][m]
    #pragma unroll
    for (int r = 0; r < 4; r++) {
        int idx = t + r * 256;
        int m = idx >> 4;
        int c = (idx & 15) * 4;
        float4 v = *(const float4*)(qb + (size_t)(q0 + m) * rowstride + c);
        Qt[(c + 0) * 68 + m] = v.x;
        Qt[(c + 1) * 68 + m] = v.y;
        Qt[(c + 2) * 68 + m] = v.z;
        Qt[(c + 3) * 68 + m] = v.w;
    }

    float o[4][4] = {};
    float m_run[4], l_run[4];
    #pragma unroll
    for (int i = 0; i < 4; i++) { m_run[i] = -1e30f; l_run[i] = 0.0f; }

    for (int kt = 0; kt < SEQ; kt += 64) {
        __syncthreads();   // prior PV reads of KPt/Vs complete (also orders Qt on iter 0)

        // Load K tile transposed into KPt, V tile natural into Vs
        #pragma unroll
        for (int r = 0; r < 4; r++) {
            int idx = t + r * 256;
            int m = idx >> 4;
            int c = (idx & 15) * 4;
            float4 kv = *(const float4*)(kb + (size_t)(kt + m) * rowstride + c);
            KPt[(c + 0) * 68 + m] = kv.x;
            KPt[(c + 1) * 68 + m] = kv.y;
            KPt[(c + 2) * 68 + m] = kv.z;
            KPt[(c + 3) * 68 + m] = kv.w;
            float4 vv = *(const float4*)(vb + (size_t)(kt + m) * rowstride + c);
            *(float4*)&Vs[m * 64 + c] = vv;
        }
        __syncthreads();

        // S = Q K^T  (4x4 per thread)
        float s[4][4] = {};
        #pragma unroll 16
        for (int d = 0; d < 64; d++) {
            float4 a = *(const float4*)&Qt[d * 68 + ty * 4];
            float4 q = *(const float4*)&KPt[d * 68 + tx * 4];
            float af[4] = {a.x, a.y, a.z, a.w};
            float bf[4] = {q.x, q.y, q.z, q.w};
            #pragma unroll
            for (int i = 0; i < 4; i++)
                #pragma unroll
                for (int j = 0; j < 4; j++)
                    s[i][j] += af[i] * bf[j];
        }

        // Online softmax (rows live in 16-lane half-warp groups)
        float corr[4];
        #pragma unroll
        for (int i = 0; i < 4; i++) {
            #pragma unroll
            for (int j = 0; j < 4; j++) s[i][j] *= QKSCALE;
            float mm = fmaxf(fmaxf(s[i][0], s[i][1]), fmaxf(s[i][2], s[i][3]));
            #pragma unroll
            for (int off = 8; off > 0; off >>= 1)
                mm = fmaxf(mm, __shfl_xor_sync(0xffffffffu, mm, off));
            float mn = fmaxf(m_run[i], mm);
            corr[i] = __expf(m_run[i] - mn);
            m_run[i] = mn;
            float ls = 0.0f;
            #pragma unroll
            for (int j = 0; j < 4; j++) {
                s[i][j] = __expf(s[i][j] - mn);
                ls += s[i][j];
            }
            #pragma unroll
            for (int off = 8; off > 0; off >>= 1)
                ls += __shfl_xor_sync(0xffffffffu, ls, off);
            l_run[i] = l_run[i] * corr[i] + ls;
            #pragma unroll
            for (int j = 0; j < 4; j++) o[i][j] *= corr[i];
        }

        __syncthreads();   // all threads done reading K from KPt

        // Write P transposed into KPt: P[m][k] -> KPt[k][m]
        #pragma unroll
        for (int i = 0; i < 4; i++)
            #pragma unroll
            for (int j = 0; j < 4; j++)
                KPt[(tx * 4 + j) * 68 + (ty * 4 + i)] = s[i][j];
        __syncthreads();

        // O += P V
        #pragma unroll 16
        for (int k2 = 0; k2 < 64; k2++) {
            float4 a = *(const float4*)&KPt[k2 * 68 + ty * 4];
            float4 v = *(const float4*)&Vs[k2 * 64 + tx * 4];
            float af[4] = {a.x, a.y, a.z, a.w};
            float vf[4] = {v.x, v.y, v.z, v.w};
            #pragma unroll
            for (int i = 0; i < 4; i++)
                #pragma unroll
                for (int j = 0; j < 4; j++)
                    o[i][j] += af[i] * vf[j];
        }
    }

    // Epilogue: normalize and write [B, N, E] layout (heads interleaved)
    #pragma unroll
    for (int i = 0; i < 4; i++) {
        float inv = 1.0f / l_run[i];
        int n = q0 + ty * 4 + i;
        float4 res;
        res.x = o[i][0] * inv;
        res.y = o[i][1] * inv;
        res.z = o[i][2] * inv;
        res.w = o[i][3] * inv;
        *(float4*)&out[((size_t)(b * SEQ + n)) * EMBED + h * HEAD_DIM + tx * 4] = res;
    }
}

// ---------------------------------------------------------------------------
extern "C" void kernel_launch(void* const* d_in, const int* in_sizes, int n_in,
                              void* d_out, int out_size)
{
    const float* x      = (const float*)d_in[0];
    const float* w_qkv  = (const float*)d_in[1];
    const float* b_qkv  = (const float*)d_in[2];
    const float* w_proj = (const float*)d_in[3];
    const float* b_proj = (const float*)d_in[4];
    float* out = (float*)d_out;

    float* qkv; cudaGetSymbolAddress((void**)&qkv, g_qkv);
    float* att; cudaGetSymbolAddress((void**)&att, g_att);

    const int M = BATCH * SEQ;   // 4096
    const int smem_attn = (2 * 64 * 68 + 64 * 64) * 4;  // 51200 B

    cudaFuncSetAttribute(attn_kernel,
                         cudaFuncAttributeMaxDynamicSharedMemorySize, smem_attn);

    // 1) QKV projection: [4096, 3072] = x[4096,1024] @ w_qkv^T + b_qkv
    dim3 g1(3 * EMBED / 128, M / 128);
    sgemm_nt_bias<128, 128, 8><<<g1, 256>>>(x, w_qkv, b_qkv, qkv,
                                            M, 3 * EMBED, EMBED);

    // 2) Fused multi-head attention -> g_att [4096, 1024]
    dim3 g2(SEQ / 64, HEADS, BATCH);
    attn_kernel<<<g2, 256, smem_attn>>>(qkv, att);

    // 3) Output projection: [4096, 1024] = att @ w_proj^T + b_proj
    dim3 g3(EMBED / 128, M / 128);
    sgemm_nt_bias<128, 128, 8><<<g3, 256>>>(att, w_proj, b_proj, out,
                                            M, EMBED, EMBED);
}

// round 3
// speedup vs baseline: 1.2847x; 1.2847x over previous
#include <cuda_runtime.h>
#include <cuda_bf16.h>
#include <cstdint>

#define EMBED    1024
#define HEADS    16
#define HEAD_DIM 64
#define SEQ      2048
#define BATCH    2
#define QKSCALE  0.125f
#define MTOT     (BATCH * SEQ)    // 4096

// ------------------------------ scratch ------------------------------------
__device__ float g_qkv[(size_t)MTOT * 3 * EMBED];
__device__ __nv_bfloat16 g_xhi[(size_t)MTOT * EMBED];
__device__ __nv_bfloat16 g_xlo[(size_t)MTOT * EMBED];
__device__ __nv_bfloat16 g_wqh[(size_t)3 * EMBED * EMBED];
__device__ __nv_bfloat16 g_wql[(size_t)3 * EMBED * EMBED];
__device__ __nv_bfloat16 g_wph[(size_t)EMBED * EMBED];
__device__ __nv_bfloat16 g_wpl[(size_t)EMBED * EMBED];
__device__ __nv_bfloat16 g_ahi[(size_t)MTOT * EMBED];
__device__ __nv_bfloat16 g_alo[(size_t)MTOT * EMBED];

// --------------------------- PTX helpers (sm_80-compatible) -----------------
__device__ __forceinline__ uint32_t smem_u32(const void* p) {
    uint32_t a;
    asm("{ .reg .u64 t; cvta.to.shared.u64 t, %1; cvt.u32.u64 %0, t; }" : "=r"(a) : "l"(p));
    return a;
}
__device__ __forceinline__ void cpasync16(uint32_t s, const void* g) {
    asm volatile("cp.async.cg.shared.global [%0], [%1], 16;" :: "r"(s), "l"(g));
}
__device__ __forceinline__ void ldsm4(uint32_t* a, uint32_t addr) {
    asm volatile("ldmatrix.sync.aligned.m8n8.x4.shared.b16 {%0,%1,%2,%3}, [%4];"
                 : "=r"(a[0]), "=r"(a[1]), "=r"(a[2]), "=r"(a[3]) : "r"(addr));
}
__device__ __forceinline__ void ldsm2(uint32_t* b, uint32_t addr) {
    asm volatile("ldmatrix.sync.aligned.m8n8.x2.shared.b16 {%0,%1}, [%2];"
                 : "=r"(b[0]), "=r"(b[1]) : "r"(addr));
}
__device__ __forceinline__ void mma16816(float* c, const uint32_t* a, const uint32_t* b) {
    asm volatile(
        "mma.sync.aligned.m16n8k16.row.col.f32.bf16.bf16.f32 "
        "{%0,%1,%2,%3},{%4,%5,%6,%7},{%8,%9},{%0,%1,%2,%3};"
        : "+f"(c[0]), "+f"(c[1]), "+f"(c[2]), "+f"(c[3])
        : "r"(a[0]), "r"(a[1]), "r"(a[2]), "r"(a[3]), "r"(b[0]), "r"(b[1]));
}

// -------------------- fp32 -> (bf16 hi, bf16 lo) split ----------------------
__global__ __launch_bounds__(256)
void split_kernel(const float* __restrict__ in, __nv_bfloat16* __restrict__ hi,
                  __nv_bfloat16* __restrict__ lo, int n4)
{
    int i = blockIdx.x * blockDim.x + threadIdx.x;
    if (i >= n4) return;
    float4 v = ((const float4*)in)[i];
    __nv_bfloat16 h0 = __float2bfloat16(v.x), h1 = __float2bfloat16(v.y);
    __nv_bfloat16 h2 = __float2bfloat16(v.z), h3 = __float2bfloat16(v.w);
    __nv_bfloat16 l0 = __float2bfloat16(v.x - __bfloat162float(h0));
    __nv_bfloat16 l1 = __float2bfloat16(v.y - __bfloat162float(h1));
    __nv_bfloat16 l2 = __float2bfloat16(v.z - __bfloat162float(h2));
    __nv_bfloat16 l3 = __float2bfloat16(v.w - __bfloat162float(h3));
    uint2 H, L;
    H.x = ((uint32_t)__bfloat16_as_ushort(h1) << 16) | __bfloat16_as_ushort(h0);
    H.y = ((uint32_t)__bfloat16_as_ushort(h3) << 16) | __bfloat16_as_ushort(h2);
    L.x = ((uint32_t)__bfloat16_as_ushort(l1) << 16) | __bfloat16_as_ushort(l0);
    L.y = ((uint32_t)__bfloat16_as_ushort(l3) << 16) | __bfloat16_as_ushort(l2);
    ((uint2*)hi)[i] = H;
    ((uint2*)lo)[i] = L;
}

// ----------- mma.sync bf16x3 GEMM: C = A W^T + bias (fp32 out) --------------
// A[M,K], W[N,K] as bf16 hi/lo (K-contiguous). 128x128 tile, BK=32,
// 256 threads = 8 warps, warp tile 64x32. 2-stage cp.async pipeline.
#define ROWB  80                     // padded smem row stride in bytes (32 bf16 + 8 pad)
#define TILEB (128 * ROWB)           // 10240 B per operand tile

__global__ __launch_bounds__(256)
void gemm_mma(const __nv_bfloat16* __restrict__ Ahi, const __nv_bfloat16* __restrict__ Alo,
              const __nv_bfloat16* __restrict__ Bhi, const __nv_bfloat16* __restrict__ Blo,
              const float* __restrict__ bias, float* __restrict__ C,
              int M, int N, int K)
{
    extern __shared__ char smem[];
    const uint32_t sbase = smem_u32(smem);

    const int t = threadIdx.x;
    const int lane = t & 31, wid = t >> 5;
    const int row0 = blockIdx.y * 128, col0 = blockIdx.x * 128;
    const int m0 = (wid >> 2) * 64;    // warp row offset in tile
    const int n0 = (wid & 3) * 32;     // warp col offset in tile

    // loader mapping: each thread: row r, two 16B chunks
    const int lr = t >> 1;
    const int cb = (t & 1) * 2;

    float c[4][4][4] = {};

    const int KT = K / 32;

    auto issue = [&](int kt, int buf) {
        const uint32_t sb = sbase + buf * 4 * TILEB;
        const size_t kel = (size_t)kt * 32 + cb * 8;
        #pragma unroll
        for (int cc = 0; cc < 2; cc++) {
            const uint32_t so = lr * ROWB + (cb + cc) * 16;
            const size_t go = kel + cc * 8;
            cpasync16(sb + 0 * TILEB + so, Ahi + (size_t)(row0 + lr) * K + go);
            cpasync16(sb + 1 * TILEB + so, Alo + (size_t)(row0 + lr) * K + go);
            cpasync16(sb + 2 * TILEB + so, Bhi + (size_t)(col0 + lr) * K + go);
            cpasync16(sb + 3 * TILEB + so, Blo + (size_t)(col0 + lr) * K + go);
        }
        asm volatile("cp.async.commit_group;" ::: "memory");
    };

    issue(0, 0);

    for (int kt = 0; kt < KT; kt++) {
        if (kt + 1 < KT) {
            issue(kt + 1, (kt + 1) & 1);
            asm volatile("cp.async.wait_group 1;" ::: "memory");
        } else {
            asm volatile("cp.async.wait_group 0;" ::: "memory");
        }
        __syncthreads();

        const uint32_t sb  = sbase + (kt & 1) * 4 * TILEB;
        const uint32_t aAh = sb;
        const uint32_t aAl = sb + TILEB;
        const uint32_t aBh = sb + 2 * TILEB;
        const uint32_t aBl = sb + 3 * TILEB;

        #pragma unroll
        for (int ks = 0; ks < 2; ks++) {
            const uint32_t ko = ks * 32;                       // 16 bf16 = 32 B
            const uint32_t arow = (m0 + (lane & 15)) * ROWB + ko + (lane >> 4) * 16;
            const uint32_t brow = (n0 + (lane & 7)) * ROWB + ko + ((lane >> 3) & 1) * 16;

            uint32_t ah[4][4], al[4][4], bh[4][2], bl[4][2];
            #pragma unroll
            for (int i = 0; i < 4; i++) ldsm4(ah[i], aAh + arow + i * 16 * ROWB);
            #pragma unroll
            for (int j = 0; j < 4; j++) ldsm2(bh[j], aBh + brow + j * 8 * ROWB);
            #pragma unroll
            for (int i = 0; i < 4; i++)
                #pragma unroll
                for (int j = 0; j < 4; j++) mma16816(c[i][j], ah[i], bh[j]);

            #pragma unroll
            for (int j = 0; j < 4; j++) ldsm2(bl[j], aBl + brow + j * 8 * ROWB);
            #pragma unroll
            for (int i = 0; i < 4; i++)
                #pragma unroll
                for (int j = 0; j < 4; j++) mma16816(c[i][j], ah[i], bl[j]);

            #pragma unroll
            for (int i = 0; i < 4; i++) ldsm4(al[i], aAl + arow + i * 16 * ROWB);
            #pragma unroll
            for (int i = 0; i < 4; i++)
                #pragma unroll
                for (int j = 0; j < 4; j++) mma16816(c[i][j], al[i], bh[j]);
        }
        __syncthreads();
    }

    // epilogue: bias + fp32 store
    #pragma unroll
    for (int j = 0; j < 4; j++) {
        const int col = col0 + n0 + j * 8 + (lane & 3) * 2;
        const float2 bb = *(const float2*)&bias[col];
        #pragma unroll
        for (int i = 0; i < 4; i++) {
            const int r0 = row0 + m0 + i * 16 + (lane >> 2);
            float2 v0 = { c[i][j][0] + bb.x, c[i][j][1] + bb.y };
            float2 v1 = { c[i][j][2] + bb.x, c[i][j][3] + bb.y };
            *(float2*)&C[(size_t)r0 * N + col]       = v0;
            *(float2*)&C[(size_t)(r0 + 8) * N + col] = v1;
        }
    }
}

// ------------- fused fp32 flash attention (epilogue -> bf16 hi/lo) ----------
__global__ __launch_bounds__(256)
void attn_kernel(const float* __restrict__ qkv,
                 __nv_bfloat16* __restrict__ ohi, __nv_bfloat16* __restrict__ olo)
{
    extern __shared__ float sm[];
    float* Qt  = sm;
    float* KPt = sm + 64 * 68;
    float* Vs  = sm + 2 * 64 * 68;

    const int t  = threadIdx.x;
    const int tx = t & 15;
    const int ty = t >> 4;
    const int qt = blockIdx.x, h = blockIdx.y, b = blockIdx.z;

    const size_t rowstride = 3 * EMBED;
    const float* qb = qkv + (size_t)b * SEQ * rowstride + (size_t)h * HEAD_DIM;
    const float* kb = qb + EMBED;
    const float* vb = qb + 2 * EMBED;
    const int q0 = qt * 64;

    #pragma unroll
    for (int r = 0; r < 4; r++) {
        int idx = t + r * 256;
        int m = idx >> 4;
        int cc = (idx & 15) * 4;
        float4 v = *(const float4*)(qb + (size_t)(q0 + m) * rowstride + cc);
        Qt[(cc + 0) * 68 + m] = v.x; Qt[(cc + 1) * 68 + m] = v.y;
        Qt[(cc + 2) * 68 + m] = v.z; Qt[(cc + 3) * 68 + m] = v.w;
    }

    float o[4][4] = {};
    float m_run[4], l_run[4];
    #pragma unroll
    for (int i = 0; i < 4; i++) { m_run[i] = -1e30f; l_run[i] = 0.0f; }

    for (int kt = 0; kt < SEQ; kt += 64) {
        __syncthreads();
        #pragma unroll
        for (int r = 0; r < 4; r++) {
            int idx = t + r * 256;
            int m = idx >> 4;
            int cc = (idx & 15) * 4;
            float4 kv = *(const float4*)(kb + (size_t)(kt + m) * rowstride + cc);
            KPt[(cc + 0) * 68 + m] = kv.x; KPt[(cc + 1) * 68 + m] = kv.y;
            KPt[(cc + 2) * 68 + m] = kv.z; KPt[(cc + 3) * 68 + m] = kv.w;
            float4 vv = *(const float4*)(vb + (size_t)(kt + m) * rowstride + cc);
            *(float4*)&Vs[m * 64 + cc] = vv;
        }
        __syncthreads();

        float s[4][4] = {};
        #pragma unroll 16
        for (int d = 0; d < 64; d++) {
            float4 a = *(const float4*)&Qt[d * 68 + ty * 4];
            float4 q = *(const float4*)&KPt[d * 68 + tx * 4];
            float af[4] = {a.x, a.y, a.z, a.w};
            float bf[4] = {q.x, q.y, q.z, q.w};
            #pragma unroll
            for (int i = 0; i < 4; i++)
                #pragma unroll
                for (int j = 0; j < 4; j++)
                    s[i][j] += af[i] * bf[j];
        }

        float corr[4];
        #pragma unroll
        for (int i = 0; i < 4; i++) {
            #pragma unroll
            for (int j = 0; j < 4; j++) s[i][j] *= QKSCALE;
            float mm = fmaxf(fmaxf(s[i][0], s[i][1]), fmaxf(s[i][2], s[i][3]));
            #pragma unroll
            for (int off = 8; off > 0; off >>= 1)
                mm = fmaxf(mm, __shfl_xor_sync(0xffffffffu, mm, off));
            float mn = fmaxf(m_run[i], mm);
            corr[i] = __expf(m_run[i] - mn);
            m_run[i] = mn;
            float ls = 0.0f;
            #pragma unroll
            for (int j = 0; j < 4; j++) { s[i][j] = __expf(s[i][j] - mn); ls += s[i][j]; }
            #pragma unroll
            for (int off = 8; off > 0; off >>= 1)
                ls += __shfl_xor_sync(0xffffffffu, ls, off);
            l_run[i] = l_run[i] * corr[i] + ls;
            #pragma unroll
            for (int j = 0; j < 4; j++) o[i][j] *= corr[i];
        }

        __syncthreads();
        #pragma unroll
        for (int i = 0; i < 4; i++)
            #pragma unroll
            for (int j = 0; j < 4; j++)
                KPt[(tx * 4 + j) * 68 + (ty * 4 + i)] = s[i][j];
        __syncthreads();

        #pragma unroll 16
        for (int k2 = 0; k2 < 64; k2++) {
            float4 a = *(const float4*)&KPt[k2 * 68 + ty * 4];
            float4 v = *(const float4*)&Vs[k2 * 64 + tx * 4];
            float af[4] = {a.x, a.y, a.z, a.w};
            float vf[4] = {v.x, v.y, v.z, v.w};
            #pragma unroll
            for (int i = 0; i < 4; i++)
                #pragma unroll
                for (int j = 0; j < 4; j++)
                    o[i][j] += af[i] * vf[j];
        }
    }

    #pragma unroll
    for (int i = 0; i < 4; i++) {
        float inv = 1.0f / l_run[i];
        int n = q0 + ty * 4 + i;
        float v[4];
        #pragma unroll
        for (int j = 0; j < 4; j++) v[j] = o[i][j] * inv;
        uint2 H, L;
        __nv_bfloat16 h0 = __float2bfloat16(v[0]), h1 = __float2bfloat16(v[1]);
        __nv_bfloat16 h2 = __float2bfloat16(v[2]), h3 = __float2bfloat16(v[3]);
        __nv_bfloat16 l0 = __float2bfloat16(v[0] - __bfloat162float(h0));
        __nv_bfloat16 l1 = __float2bfloat16(v[1] - __bfloat162float(h1));
        __nv_bfloat16 l2 = __float2bfloat16(v[2] - __bfloat162float(h2));
        __nv_bfloat16 l3 = __float2bfloat16(v[3] - __bfloat162float(h3));
        H.x = ((uint32_t)__bfloat16_as_ushort(h1) << 16) | __bfloat16_as_ushort(h0);
        H.y = ((uint32_t)__bfloat16_as_ushort(h3) << 16) | __bfloat16_as_ushort(h2);
        L.x = ((uint32_t)__bfloat16_as_ushort(l1) << 16) | __bfloat16_as_ushort(l0);
        L.y = ((uint32_t)__bfloat16_as_ushort(l3) << 16) | __bfloat16_as_ushort(l2);
        const size_t idx = ((size_t)(b * SEQ + n)) * EMBED + h * HEAD_DIM + tx * 4;
        *(uint2*)&ohi[idx] = H;
        *(uint2*)&olo[idx] = L;
    }
}

// ---------------------------------------------------------------------------
extern "C" void kernel_launch(void* const* d_in, const int* in_sizes, int n_in,
                              void* d_out, int out_size)
{
    const float* x      = (const float*)d_in[0];
    const float* w_qkv  = (const float*)d_in[1];
    const float* b_qkv  = (const float*)d_in[2];
    const float* w_proj = (const float*)d_in[3];
    const float* b_proj = (const float*)d_in[4];
    float* out = (float*)d_out;

    float* qkv;
    __nv_bfloat16 *xhi, *xlo, *wqh, *wql, *wph, *wpl, *ahi, *alo;
    cudaGetSymbolAddress((void**)&qkv, g_qkv);
    cudaGetSymbolAddress((void**)&xhi, g_xhi);
    cudaGetSymbolAddress((void**)&xlo, g_xlo);
    cudaGetSymbolAddress((void**)&wqh, g_wqh);
    cudaGetSymbolAddress((void**)&wql, g_wql);
    cudaGetSymbolAddress((void**)&wph, g_wph);
    cudaGetSymbolAddress((void**)&wpl, g_wpl);
    cudaGetSymbolAddress((void**)&ahi, g_ahi);
    cudaGetSymbolAddress((void**)&alo, g_alo);

    const int M = MTOT;
    const int smem_gemm = 2 * 4 * TILEB;                 // 81920 B
    const int smem_attn = (2 * 64 * 68 + 64 * 64) * 4;   // 51200 B

    cudaFuncSetAttribute(gemm_mma, cudaFuncAttributeMaxDynamicSharedMemorySize, smem_gemm);
    cudaFuncSetAttribute(attn_kernel, cudaFuncAttributeMaxDynamicSharedMemorySize, smem_attn);

    // splits
    {
        int n4 = M * EMBED / 4;
        split_kernel<<<(n4 + 255) / 256, 256>>>(x, xhi, xlo, n4);
        n4 = 3 * EMBED * EMBED / 4;
        split_kernel<<<(n4 + 255) / 256, 256>>>(w_qkv, wqh, wql, n4);
        n4 = EMBED * EMBED / 4;
        split_kernel<<<(n4 + 255) / 256, 256>>>(w_proj, wph, wpl, n4);
    }

    // 1) QKV projection [4096, 3072]
    {
        dim3 g(3 * EMBED / 128, M / 128);
        gemm_mma<<<g, 256, smem_gemm>>>(xhi, xlo, wqh, wql, b_qkv, qkv,
                                        M, 3 * EMBED, EMBED);
    }

    // 2) attention -> bf16 hi/lo directly
    {
        dim3 g(SEQ / 64, HEADS, BATCH);
        attn_kernel<<<g, 256, smem_attn>>>(qkv, ahi, alo);
    }

    // 3) proj GEMM [4096, 1024] -> out
    {
        dim3 g(EMBED / 128, M / 128);
        gemm_mma<<<g, 256, smem_gemm>>>(ahi, alo, wph, wpl, b_proj, out,
                                        M, EMBED, EMBED);
    }
}

// round 5
// speedup vs baseline: 2.2631x; 1.7615x over previous
#include <cuda_runtime.h>
#include <cuda_bf16.h>
#include <cstdint>

#define EMBED    1024
#define HEADS    16
#define HEAD_DIM 64
#define SEQ      2048
#define BATCH    2
#define MTOT     (BATCH * SEQ)    // 4096

// ------------------------------ scratch ------------------------------------
__device__ __nv_bfloat16 g_xhi[(size_t)MTOT * EMBED];
__device__ __nv_bfloat16 g_xlo[(size_t)MTOT * EMBED];
__device__ __nv_bfloat16 g_wqh[(size_t)3 * EMBED * EMBED];
__device__ __nv_bfloat16 g_wql[(size_t)3 * EMBED * EMBED];
__device__ __nv_bfloat16 g_wph[(size_t)EMBED * EMBED];
__device__ __nv_bfloat16 g_wpl[(size_t)EMBED * EMBED];
__device__ __nv_bfloat16 g_qh[(size_t)MTOT * 3 * EMBED];   // qkv hi
__device__ __nv_bfloat16 g_ql[(size_t)MTOT * 3 * EMBED];   // qkv lo
__device__ __nv_bfloat16 g_ahi[(size_t)MTOT * EMBED];
__device__ __nv_bfloat16 g_alo[(size_t)MTOT * EMBED];

// --------------------------- PTX helpers ------------------------------------
__device__ __forceinline__ uint32_t smem_u32(const void* p) {
    uint32_t a;
    asm("{ .reg .u64 t; cvta.to.shared.u64 t, %1; cvt.u32.u64 %0, t; }" : "=r"(a) : "l"(p));
    return a;
}
__device__ __forceinline__ void cpasync16(uint32_t s, const void* g) {
    asm volatile("cp.async.cg.shared.global [%0], [%1], 16;" :: "r"(s), "l"(g));
}
__device__ __forceinline__ void ldsm4(uint32_t* a, uint32_t addr) {
    asm volatile("ldmatrix.sync.aligned.m8n8.x4.shared.b16 {%0,%1,%2,%3}, [%4];"
                 : "=r"(a[0]), "=r"(a[1]), "=r"(a[2]), "=r"(a[3]) : "r"(addr));
}
__device__ __forceinline__ void ldsm2(uint32_t* b, uint32_t addr) {
    asm volatile("ldmatrix.sync.aligned.m8n8.x2.shared.b16 {%0,%1}, [%2];"
                 : "=r"(b[0]), "=r"(b[1]) : "r"(addr));
}
__device__ __forceinline__ void ldsm2t(uint32_t* b, uint32_t addr) {
    asm volatile("ldmatrix.sync.aligned.m8n8.x2.trans.shared.b16 {%0,%1}, [%2];"
                 : "=r"(b[0]), "=r"(b[1]) : "r"(addr));
}
__device__ __forceinline__ void mma16816(float* c, const uint32_t* a, const uint32_t* b) {
    asm volatile(
        "mma.sync.aligned.m16n8k16.row.col.f32.bf16.bf16.f32 "
        "{%0,%1,%2,%3},{%4,%5,%6,%7},{%8,%9},{%0,%1,%2,%3};"
        : "+f"(c[0]), "+f"(c[1]), "+f"(c[2]), "+f"(c[3])
        : "r"(a[0]), "r"(a[1]), "r"(a[2]), "r"(a[3]), "r"(b[0]), "r"(b[1]));
}
__device__ __forceinline__ uint32_t pack2(float a, float b) {
    __nv_bfloat162 t = __floats2bfloat162_rn(a, b);
    return *(uint32_t*)&t;
}
__device__ __forceinline__ void split2(float a, float b, uint32_t& H, uint32_t& L) {
    __nv_bfloat16 ha = __float2bfloat16(a), hb = __float2bfloat16(b);
    float la = a - __bfloat162float(ha), lb = b - __bfloat162float(hb);
    H = ((uint32_t)__bfloat16_as_ushort(hb) << 16) | __bfloat16_as_ushort(ha);
    L = pack2(la, lb);
}

// -------------------- fp32 -> (bf16 hi, bf16 lo) split ----------------------
__global__ __launch_bounds__(256)
void split_kernel(const float* __restrict__ in, __nv_bfloat16* __restrict__ hi,
                  __nv_bfloat16* __restrict__ lo, int n4)
{
    int i = blockIdx.x * blockDim.x + threadIdx.x;
    if (i >= n4) return;
    float4 v = ((const float4*)in)[i];
    uint2 H, L;
    split2(v.x, v.y, H.x, L.x);
    split2(v.z, v.w, H.y, L.y);
    ((uint2*)hi)[i] = H;
    ((uint2*)lo)[i] = L;
}

// ----------- mma.sync bf16x3 GEMM: C = A W^T + bias -------------------------
// MODE 0: fp32 out. MODE 1: bf16 hi/lo out, cols < 1024 scaled by 0.125 (Q).
#define ROWB  80
#define TILEB (128 * ROWB)

template<int MODE>
__global__ __launch_bounds__(256)
void gemm_mma(const __nv_bfloat16* __restrict__ Ahi, const __nv_bfloat16* __restrict__ Alo,
              const __nv_bfloat16* __restrict__ Bhi, const __nv_bfloat16* __restrict__ Blo,
              const float* __restrict__ bias, float* __restrict__ C,
              __nv_bfloat16* __restrict__ Chi, __nv_bfloat16* __restrict__ Clo,
              int M, int N, int K)
{
    extern __shared__ char smem[];
    const uint32_t sbase = smem_u32(smem);

    const int t = threadIdx.x;
    const int lane = t & 31, wid = t >> 5;
    const int row0 = blockIdx.y * 128, col0 = blockIdx.x * 128;
    const int m0 = (wid >> 2) * 64;
    const int n0 = (wid & 3) * 32;
    const int lr = t >> 1;
    const int cb = (t & 1) * 2;

    float c[4][4][4] = {};
    const int KT = K / 32;

    auto issue = [&](int kt, int buf) {
        const uint32_t sb = sbase + buf * 4 * TILEB;
        const size_t kel = (size_t)kt * 32 + cb * 8;
        #pragma unroll
        for (int cc = 0; cc < 2; cc++) {
            const uint32_t so = lr * ROWB + (cb + cc) * 16;
            const size_t go = kel + cc * 8;
            cpasync16(sb + 0 * TILEB + so, Ahi + (size_t)(row0 + lr) * K + go);
            cpasync16(sb + 1 * TILEB + so, Alo + (size_t)(row0 + lr) * K + go);
            cpasync16(sb + 2 * TILEB + so, Bhi + (size_t)(col0 + lr) * K + go);
            cpasync16(sb + 3 * TILEB + so, Blo + (size_t)(col0 + lr) * K + go);
        }
        asm volatile("cp.async.commit_group;" ::: "memory");
    };

    issue(0, 0);

    for (int kt = 0; kt < KT; kt++) {
        if (kt + 1 < KT) {
            issue(kt + 1, (kt + 1) & 1);
            asm volatile("cp.async.wait_group 1;" ::: "memory");
        } else {
            asm volatile("cp.async.wait_group 0;" ::: "memory");
        }
        __syncthreads();

        const uint32_t sb  = sbase + (kt & 1) * 4 * TILEB;
        const uint32_t aAh = sb, aAl = sb + TILEB, aBh = sb + 2 * TILEB, aBl = sb + 3 * TILEB;

        #pragma unroll
        for (int ks = 0; ks < 2; ks++) {
            const uint32_t ko = ks * 32;
            const uint32_t arow = (m0 + (lane & 15)) * ROWB + ko + (lane >> 4) * 16;
            const uint32_t brow = (n0 + (lane & 7)) * ROWB + ko + ((lane >> 3) & 1) * 16;

            uint32_t ah[4][4], al[4][4], bh[4][2], bl[4][2];
            #pragma unroll
            for (int i = 0; i < 4; i++) ldsm4(ah[i], aAh + arow + i * 16 * ROWB);
            #pragma unroll
            for (int j = 0; j < 4; j++) ldsm2(bh[j], aBh + brow + j * 8 * ROWB);
            #pragma unroll
            for (int i = 0; i < 4; i++)
                #pragma unroll
                for (int j = 0; j < 4; j++) mma16816(c[i][j], ah[i], bh[j]);
            #pragma unroll
            for (int j = 0; j < 4; j++) ldsm2(bl[j], aBl + brow + j * 8 * ROWB);
            #pragma unroll
            for (int i = 0; i < 4; i++)
                #pragma unroll
                for (int j = 0; j < 4; j++) mma16816(c[i][j], ah[i], bl[j]);
            #pragma unroll
            for (int i = 0; i < 4; i++) ldsm4(al[i], aAl + arow + i * 16 * ROWB);
            #pragma unroll
            for (int i = 0; i < 4; i++)
                #pragma unroll
                for (int j = 0; j < 4; j++) mma16816(c[i][j], al[i], bh[j]);
        }
        __syncthreads();
    }

    #pragma unroll
    for (int j = 0; j < 4; j++) {
        const int col = col0 + n0 + j * 8 + (lane & 3) * 2;
        const float2 bb = *(const float2*)&bias[col];
        const float sc = (MODE == 1 && col < EMBED) ? 0.125f : 1.0f;
        #pragma unroll
        for (int i = 0; i < 4; i++) {
            const int r0 = row0 + m0 + i * 16 + (lane >> 2);
            float v0 = (c[i][j][0] + bb.x) * sc, v1 = (c[i][j][1] + bb.y) * sc;
            float v2 = (c[i][j][2] + bb.x) * sc, v3 = (c[i][j][3] + bb.y) * sc;
            if (MODE == 0) {
                *(float2*)&C[(size_t)r0 * N + col]       = make_float2(v0, v1);
                *(float2*)&C[(size_t)(r0 + 8) * N + col] = make_float2(v2, v3);
            } else {
                uint32_t H, L;
                split2(v0, v1, H, L);
                *(uint32_t*)&Chi[(size_t)r0 * N + col] = H;
                *(uint32_t*)&Clo[(size_t)r0 * N + col] = L;
                split2(v2, v3, H, L);
                *(uint32_t*)&Chi[(size_t)(r0 + 8) * N + col] = H;
                *(uint32_t*)&Clo[(size_t)(r0 + 8) * N + col] = L;
            }
        }
    }
}

// -------------- mma.sync bf16x3 flash attention -----------------------------
// CTA: (q-tile 128, head, batch). 8 warps x 16 rows. KV tiles of 128.
#define PDB 144   // padded smem row stride bytes (64 bf16 data + 16B pad)
#define QT  (128 * PDB)          // 18432 B per [128][64] tile
#define KVB (4 * QT)             // K/V hi/lo per buffer

__global__ __launch_bounds__(256)
void attn_mma(const __nv_bfloat16* __restrict__ qh, const __nv_bfloat16* __restrict__ ql,
              __nv_bfloat16* __restrict__ ohi, __nv_bfloat16* __restrict__ olo)
{
    extern __shared__ char smem[];
    const uint32_t sQh = smem_u32(smem);
    const uint32_t sQl = sQh + QT;
    const uint32_t sKV = sQl + QT;    // two buffers of [Kh,Kl,Vh,Vl]

    const int t = threadIdx.x, lane = t & 31, wid = t >> 5;
    const int qt = blockIdx.x, h = blockIdx.y, b = blockIdx.z;
    const int q0 = qt * 128;
    const size_t rowE = 3 * EMBED;
    const __nv_bfloat16* qbh = qh + (size_t)b * SEQ * rowE + h * HEAD_DIM;
    const __nv_bfloat16* qbl = ql + (size_t)b * SEQ * rowE + h * HEAD_DIM;

    const int lr = t >> 1;          // 0..127 row
    const int cb = (t & 1) * 4;     // 4 chunks of 16B per thread -> 128B/row

    // group 0: Q tiles (full 128 B per row)
    #pragma unroll
    for (int cc = 0; cc < 4; cc++) {
        const uint32_t so = lr * PDB + (cb + cc) * 16;
        const size_t go = (size_t)(q0 + lr) * rowE + (cb + cc) * 8;
        cpasync16(sQh + so, qbh + go);
        cpasync16(sQl + so, qbl + go);
    }
    asm volatile("cp.async.commit_group;" ::: "memory");

    auto issueKV = [&](int kt, int buf) {
        const uint32_t sb = sKV + buf * KVB;
        const size_t krow = (size_t)(kt * 128 + lr) * rowE;
        #pragma unroll
        for (int cc = 0; cc < 4; cc++) {
            const uint32_t so = lr * PDB + (cb + cc) * 16;
            const size_t gk = krow + EMBED + (cb + cc) * 8;
            const size_t gv = krow + 2 * EMBED + (cb + cc) * 8;
            cpasync16(sb + 0 * QT + so, qbh + gk);
            cpasync16(sb + 1 * QT + so, qbl + gk);
            cpasync16(sb + 2 * QT + so, qbh + gv);
            cpasync16(sb + 3 * QT + so, qbl + gv);
        }
        asm volatile("cp.async.commit_group;" ::: "memory");
    };

    issueKV(0, 0);

    float o[8][4] = {};
    float m_lo = -1e30f, m_hi = -1e30f, l_lo = 0.0f, l_hi = 0.0f;
    uint32_t qfh[4][4], qfl[4][4];

    const int NKV = SEQ / 128;
    for (int kt = 0; kt < NKV; kt++) {
        if (kt + 1 < NKV) {
            issueKV(kt + 1, (kt + 1) & 1);
            asm volatile("cp.async.wait_group 1;" ::: "memory");
        } else {
            asm volatile("cp.async.wait_group 0;" ::: "memory");
        }
        __syncthreads();

        if (kt == 0) {
            #pragma unroll
            for (int ks = 0; ks < 4; ks++) {
                const uint32_t arow = ((wid * 16) + (lane & 15)) * PDB + ks * 32 + (lane >> 4) * 16;
                ldsm4(qfh[ks], sQh + arow);
                ldsm4(qfl[ks], sQl + arow);
            }
        }

        const uint32_t sb  = sKV + (kt & 1) * KVB;
        const uint32_t aKh = sb, aKl = sb + QT, aVh = sb + 2 * QT, aVl = sb + 3 * QT;

        // ---- S = Q K^T (3-term compensated) ----
        float s[16][4] = {};
        #pragma unroll
        for (int ks = 0; ks < 4; ks++) {
            const uint32_t bbase = (lane & 7) * PDB + ks * 32 + ((lane >> 3) & 1) * 16;
            uint32_t kf[16][2];
            #pragma unroll
            for (int j = 0; j < 16; j++) ldsm2(kf[j], aKh + bbase + j * 8 * PDB);
            #pragma unroll
            for (int j = 0; j < 16; j++) mma16816(s[j], qfh[ks], kf[j]);
            #pragma unroll
            for (int j = 0; j < 16; j++) mma16816(s[j], qfl[ks], kf[j]);
            #pragma unroll
            for (int j = 0; j < 16; j++) ldsm2(kf[j], aKl + bbase + j * 8 * PDB);
            #pragma unroll
            for (int j = 0; j < 16; j++) mma16816(s[j], qfh[ks], kf[j]);
        }

        // ---- online softmax ----
        float tmax_lo = -1e30f, tmax_hi = -1e30f;
        #pragma unroll
        for (int j = 0; j < 16; j++) {
            tmax_lo = fmaxf(tmax_lo, fmaxf(s[j][0], s[j][1]));
            tmax_hi = fmaxf(tmax_hi, fmaxf(s[j][2], s[j][3]));
        }
        tmax_lo = fmaxf(tmax_lo, __shfl_xor_sync(0xffffffffu, tmax_lo, 1));
        tmax_lo = fmaxf(tmax_lo, __shfl_xor_sync(0xffffffffu, tmax_lo, 2));
        tmax_hi = fmaxf(tmax_hi, __shfl_xor_sync(0xffffffffu, tmax_hi, 1));
        tmax_hi = fmaxf(tmax_hi, __shfl_xor_sync(0xffffffffu, tmax_hi, 2));
        float mn_lo = fmaxf(m_lo, tmax_lo), mn_hi = fmaxf(m_hi, tmax_hi);
        float corr_lo = __expf(m_lo - mn_lo), corr_hi = __expf(m_hi - mn_hi);
        m_lo = mn_lo; m_hi = mn_hi;

        float sum_lo = 0.0f, sum_hi = 0.0f;
        #pragma unroll
        for (int j = 0; j < 16; j++) {
            s[j][0] = __expf(s[j][0] - m_lo); s[j][1] = __expf(s[j][1] - m_lo);
            s[j][2] = __expf(s[j][2] - m_hi); s[j][3] = __expf(s[j][3] - m_hi);
            sum_lo += s[j][0] + s[j][1];
            sum_hi += s[j][2] + s[j][3];
        }
        sum_lo += __shfl_xor_sync(0xffffffffu, sum_lo, 1);
        sum_lo += __shfl_xor_sync(0xffffffffu, sum_lo, 2);
        sum_hi += __shfl_xor_sync(0xffffffffu, sum_hi, 1);
        sum_hi += __shfl_xor_sync(0xffffffffu, sum_hi, 2);
        l_lo = l_lo * corr_lo + sum_lo;
        l_hi = l_hi * corr_hi + sum_hi;
        #pragma unroll
        for (int j = 0; j < 8; j++) {
            o[j][0] *= corr_lo; o[j][1] *= corr_lo;
            o[j][2] *= corr_hi; o[j][3] *= corr_hi;
        }

        // ---- O += P V (3-term compensated) ----
        #pragma unroll
        for (int kk = 0; kk < 8; kk++) {
            uint32_t ph[4], pl[4];
            split2(s[2*kk  ][0], s[2*kk  ][1], ph[0], pl[0]);
            split2(s[2*kk  ][2], s[2*kk  ][3], ph[1], pl[1]);
            split2(s[2*kk+1][0], s[2*kk+1][1], ph[2], pl[2]);
            split2(s[2*kk+1][2], s[2*kk+1][3], ph[3], pl[3]);

            const uint32_t vrow = (kk * 16 + (lane & 15)) * PDB;
            uint32_t vf[8][2];
            #pragma unroll
            for (int j = 0; j < 8; j++) ldsm2t(vf[j], aVh + vrow + j * 16);
            #pragma unroll
            for (int j = 0; j < 8; j++) mma16816(o[j], ph, vf[j]);
            #pragma unroll
            for (int j = 0; j < 8; j++) mma16816(o[j], pl, vf[j]);
            #pragma unroll
            for (int j = 0; j < 8; j++) ldsm2t(vf[j], aVl + vrow + j * 16);
            #pragma unroll
            for (int j = 0; j < 8; j++) mma16816(o[j], ph, vf[j]);
        }
        __syncthreads();
    }

    // ---- epilogue: normalize + bf16 hi/lo out ----
    const float inv_lo = 1.0f / l_lo, inv_hi = 1.0f / l_hi;
    const int r_lo = q0 + wid * 16 + (lane >> 2);
    const size_t obase = (size_t)(b * SEQ) * EMBED + (size_t)h * HEAD_DIM;
    #pragma unroll
    for (int j = 0; j < 8; j++) {
        const int col = j * 8 + (lane & 3) * 2;
        uint32_t H, L;
        split2(o[j][0] * inv_lo, o[j][1] * inv_lo, H, L);
        *(uint32_t*)&ohi[obase + (size_t)r_lo * EMBED + col] = H;
        *(uint32_t*)&olo[obase + (size_t)r_lo * EMBED + col] = L;
        split2(o[j][2] * inv_hi, o[j][3] * inv_hi, H, L);
        *(uint32_t*)&ohi[obase + (size_t)(r_lo + 8) * EMBED + col] = H;
        *(uint32_t*)&olo[obase + (size_t)(r_lo + 8) * EMBED + col] = L;
    }
}

// ---------------------------------------------------------------------------
extern "C" void kernel_launch(void* const* d_in, const int* in_sizes, int n_in,
                              void* d_out, int out_size)
{
    const float* x      = (const float*)d_in[0];
    const float* w_qkv  = (const float*)d_in[1];
    const float* b_qkv  = (const float*)d_in[2];
    const float* w_proj = (const float*)d_in[3];
    const float* b_proj = (const float*)d_in[4];
    float* out = (float*)d_out;

    __nv_bfloat16 *xhi, *xlo, *wqh, *wql, *wph, *wpl, *qh, *ql, *ahi, *alo;
    cudaGetSymbolAddress((void**)&xhi, g_xhi);
    cudaGetSymbolAddress((void**)&xlo, g_xlo);
    cudaGetSymbolAddress((void**)&wqh, g_wqh);
    cudaGetSymbolAddress((void**)&wql, g_wql);
    cudaGetSymbolAddress((void**)&wph, g_wph);
    cudaGetSymbolAddress((void**)&wpl, g_wpl);
    cudaGetSymbolAddress((void**)&qh, g_qh);
    cudaGetSymbolAddress((void**)&ql, g_ql);
    cudaGetSymbolAddress((void**)&ahi, g_ahi);
    cudaGetSymbolAddress((void**)&alo, g_alo);

    const int M = MTOT;
    const int smem_gemm = 2 * 4 * TILEB;       // 81920
    const int smem_attn = 2 * QT + 2 * KVB;    // 36864 + 147456 = 184320

    cudaFuncSetAttribute(gemm_mma<0>, cudaFuncAttributeMaxDynamicSharedMemorySize, smem_gemm);
    cudaFuncSetAttribute(gemm_mma<1>, cudaFuncAttributeMaxDynamicSharedMemorySize, smem_gemm);
    cudaFuncSetAttribute(attn_mma, cudaFuncAttributeMaxDynamicSharedMemorySize, smem_attn);

    // splits
    {
        int n4 = M * EMBED / 4;
        split_kernel<<<(n4 + 255) / 256, 256>>>(x, xhi, xlo, n4);
        n4 = 3 * EMBED * EMBED / 4;
        split_kernel<<<(n4 + 255) / 256, 256>>>(w_qkv, wqh, wql, n4);
        n4 = EMBED * EMBED / 4;
        split_kernel<<<(n4 + 255) / 256, 256>>>(w_proj, wph, wpl, n4);
    }

    // 1) QKV projection -> bf16 hi/lo (Q pre-scaled by 0.125)
    {
        dim3 g(3 * EMBED / 128, M / 128);
        gemm_mma<1><<<g, 256, smem_gemm>>>(xhi, xlo, wqh, wql, b_qkv,
                                           nullptr, qh, ql, M, 3 * EMBED, EMBED);
    }

    // 2) attention (tensor cores) -> bf16 hi/lo
    {
        dim3 g(SEQ / 128, HEADS, BATCH);
        attn_mma<<<g, 256, smem_attn>>>(qh, ql, ahi, alo);
    }

    // 3) proj GEMM -> fp32 out
    {
        dim3 g(EMBED / 128, M / 128);
        gemm_mma<0><<<g, 256, smem_gemm>>>(ahi, alo, wph, wpl, b_proj,
                                           out, nullptr, nullptr, M, EMBED, EMBED);
    }
}

// round 6
// speedup vs baseline: 2.4410x; 1.0786x over previous
#include <cuda_runtime.h>
#include <cuda_bf16.h>
#include <cstdint>

#define EMBED    1024
#define HEADS    16
#define HEAD_DIM 64
#define SEQ      2048
#define BATCH    2
#define MTOT     (BATCH * SEQ)    // 4096

// ------------------------------ scratch ------------------------------------
__device__ __nv_bfloat16 g_xhi[(size_t)MTOT * EMBED];
__device__ __nv_bfloat16 g_xlo[(size_t)MTOT * EMBED];
__device__ __nv_bfloat16 g_wqh[(size_t)3 * EMBED * EMBED];
__device__ __nv_bfloat16 g_wql[(size_t)3 * EMBED * EMBED];
__device__ __nv_bfloat16 g_wph[(size_t)EMBED * EMBED];
__device__ __nv_bfloat16 g_wpl[(size_t)EMBED * EMBED];
__device__ __nv_bfloat16 g_qh[(size_t)MTOT * 3 * EMBED];   // qkv hi
__device__ __nv_bfloat16 g_ql[(size_t)MTOT * 3 * EMBED];   // qkv lo
__device__ __nv_bfloat16 g_ahi[(size_t)MTOT * EMBED];
__device__ __nv_bfloat16 g_alo[(size_t)MTOT * EMBED];

// --------------------------- PTX helpers ------------------------------------
__device__ __forceinline__ uint32_t smem_u32(const void* p) {
    uint32_t a;
    asm("{ .reg .u64 t; cvta.to.shared.u64 t, %1; cvt.u32.u64 %0, t; }" : "=r"(a) : "l"(p));
    return a;
}
__device__ __forceinline__ void cpasync16(uint32_t s, const void* g) {
    asm volatile("cp.async.cg.shared.global [%0], [%1], 16;" :: "r"(s), "l"(g));
}
__device__ __forceinline__ void ldsm4(uint32_t* a, uint32_t addr) {
    asm volatile("ldmatrix.sync.aligned.m8n8.x4.shared.b16 {%0,%1,%2,%3}, [%4];"
                 : "=r"(a[0]), "=r"(a[1]), "=r"(a[2]), "=r"(a[3]) : "r"(addr));
}
__device__ __forceinline__ void ldsm2(uint32_t* b, uint32_t addr) {
    asm volatile("ldmatrix.sync.aligned.m8n8.x2.shared.b16 {%0,%1}, [%2];"
                 : "=r"(b[0]), "=r"(b[1]) : "r"(addr));
}
__device__ __forceinline__ void ldsm2t(uint32_t* b, uint32_t addr) {
    asm volatile("ldmatrix.sync.aligned.m8n8.x2.trans.shared.b16 {%0,%1}, [%2];"
                 : "=r"(b[0]), "=r"(b[1]) : "r"(addr));
}
__device__ __forceinline__ void mma16816(float* c, const uint32_t* a, const uint32_t* b) {
    asm volatile(
        "mma.sync.aligned.m16n8k16.row.col.f32.bf16.bf16.f32 "
        "{%0,%1,%2,%3},{%4,%5,%6,%7},{%8,%9},{%0,%1,%2,%3};"
        : "+f"(c[0]), "+f"(c[1]), "+f"(c[2]), "+f"(c[3])
        : "r"(a[0]), "r"(a[1]), "r"(a[2]), "r"(a[3]), "r"(b[0]), "r"(b[1]));
}
__device__ __forceinline__ uint32_t pack2(float a, float b) {
    __nv_bfloat162 t = __floats2bfloat162_rn(a, b);
    return *(uint32_t*)&t;
}
__device__ __forceinline__ void split2(float a, float b, uint32_t& H, uint32_t& L) {
    __nv_bfloat16 ha = __float2bfloat16(a), hb = __float2bfloat16(b);
    float la = a - __bfloat162float(ha), lb = b - __bfloat162float(hb);
    H = ((uint32_t)__bfloat16_as_ushort(hb) << 16) | __bfloat16_as_ushort(ha);
    L = pack2(la, lb);
}

// -------------------- fp32 -> (bf16 hi, bf16 lo) split ----------------------
__global__ __launch_bounds__(256)
void split_kernel(const float* __restrict__ in, __nv_bfloat16* __restrict__ hi,
                  __nv_bfloat16* __restrict__ lo, int n4)
{
    int i = blockIdx.x * blockDim.x + threadIdx.x;
    if (i >= n4) return;
    float4 v = ((const float4*)in)[i];
    uint2 H, L;
    split2(v.x, v.y, H.x, L.x);
    split2(v.z, v.w, H.y, L.y);
    ((uint2*)hi)[i] = H;
    ((uint2*)lo)[i] = L;
}

// ----------- mma.sync bf16x3 GEMM: C = A W^T + bias -------------------------
// MODE 0: fp32 out. MODE 1: bf16 hi/lo out, cols < 1024 scaled by 0.125 (Q).
#define ROWB  80
#define TILEB (128 * ROWB)

template<int MODE>
__global__ __launch_bounds__(256, 2)
void gemm_mma(const __nv_bfloat16* __restrict__ Ahi, const __nv_bfloat16* __restrict__ Alo,
              const __nv_bfloat16* __restrict__ Bhi, const __nv_bfloat16* __restrict__ Blo,
              const float* __restrict__ bias, float* __restrict__ C,
              __nv_bfloat16* __restrict__ Chi, __nv_bfloat16* __restrict__ Clo,
              int M, int N, int K)
{
    extern __shared__ char smem[];
    const uint32_t sbase = smem_u32(smem);

    const int t = threadIdx.x;
    const int lane = t & 31, wid = t >> 5;
    const int row0 = blockIdx.y * 128, col0 = blockIdx.x * 128;
    const int m0 = (wid >> 2) * 64;
    const int n0 = (wid & 3) * 32;
    const int lr = t >> 1;
    const int cb = (t & 1) * 2;

    float c[4][4][4] = {};
    const int KT = K / 32;

    auto issue = [&](int kt, int buf) {
        const uint32_t sb = sbase + buf * 4 * TILEB;
        const size_t kel = (size_t)kt * 32 + cb * 8;
        #pragma unroll
        for (int cc = 0; cc < 2; cc++) {
            const uint32_t so = lr * ROWB + (cb + cc) * 16;
            const size_t go = kel + cc * 8;
            cpasync16(sb + 0 * TILEB + so, Ahi + (size_t)(row0 + lr) * K + go);
            cpasync16(sb + 1 * TILEB + so, Alo + (size_t)(row0 + lr) * K + go);
            cpasync16(sb + 2 * TILEB + so, Bhi + (size_t)(col0 + lr) * K + go);
            cpasync16(sb + 3 * TILEB + so, Blo + (size_t)(col0 + lr) * K + go);
        }
        asm volatile("cp.async.commit_group;" ::: "memory");
    };

    issue(0, 0);

    for (int kt = 0; kt < KT; kt++) {
        if (kt + 1 < KT) {
            issue(kt + 1, (kt + 1) & 1);
            asm volatile("cp.async.wait_group 1;" ::: "memory");
        } else {
            asm volatile("cp.async.wait_group 0;" ::: "memory");
        }
        __syncthreads();

        const uint32_t sb  = sbase + (kt & 1) * 4 * TILEB;
        const uint32_t aAh = sb, aAl = sb + TILEB, aBh = sb + 2 * TILEB, aBl = sb + 3 * TILEB;

        #pragma unroll
        for (int ks = 0; ks < 2; ks++) {
            const uint32_t ko = ks * 32;
            const uint32_t arow = (m0 + (lane & 15)) * ROWB + ko + (lane >> 4) * 16;
            const uint32_t brow = (n0 + (lane & 7)) * ROWB + ko + ((lane >> 3) & 1) * 16;

            uint32_t ah[4][4], al[4][4], bh[4][2], bl[4][2];
            #pragma unroll
            for (int i = 0; i < 4; i++) ldsm4(ah[i], aAh + arow + i * 16 * ROWB);
            #pragma unroll
            for (int j = 0; j < 4; j++) ldsm2(bh[j], aBh + brow + j * 8 * ROWB);
            #pragma unroll
            for (int i = 0; i < 4; i++)
                #pragma unroll
                for (int j = 0; j < 4; j++) mma16816(c[i][j], ah[i], bh[j]);
            #pragma unroll
            for (int j = 0; j < 4; j++) ldsm2(bl[j], aBl + brow + j * 8 * ROWB);
            #pragma unroll
            for (int i = 0; i < 4; i++)
                #pragma unroll
                for (int j = 0; j < 4; j++) mma16816(c[i][j], ah[i], bl[j]);
            #pragma unroll
            for (int i = 0; i < 4; i++) ldsm4(al[i], aAl + arow + i * 16 * ROWB);
            #pragma unroll
            for (int i = 0; i < 4; i++)
                #pragma unroll
                for (int j = 0; j < 4; j++) mma16816(c[i][j], al[i], bh[j]);
        }
        __syncthreads();
    }

    #pragma unroll
    for (int j = 0; j < 4; j++) {
        const int col = col0 + n0 + j * 8 + (lane & 3) * 2;
        const float2 bb = *(const float2*)&bias[col];
        const float sc = (MODE == 1 && col < EMBED) ? 0.125f : 1.0f;
        #pragma unroll
        for (int i = 0; i < 4; i++) {
            const int r0 = row0 + m0 + i * 16 + (lane >> 2);
            float v0 = (c[i][j][0] + bb.x) * sc, v1 = (c[i][j][1] + bb.y) * sc;
            float v2 = (c[i][j][2] + bb.x) * sc, v3 = (c[i][j][3] + bb.y) * sc;
            if (MODE == 0) {
                *(float2*)&C[(size_t)r0 * N + col]       = make_float2(v0, v1);
                *(float2*)&C[(size_t)(r0 + 8) * N + col] = make_float2(v2, v3);
            } else {
                uint32_t H, L;
                split2(v0, v1, H, L);
                *(uint32_t*)&Chi[(size_t)r0 * N + col] = H;
                *(uint32_t*)&Clo[(size_t)r0 * N + col] = L;
                split2(v2, v3, H, L);
                *(uint32_t*)&Chi[(size_t)(r0 + 8) * N + col] = H;
                *(uint32_t*)&Clo[(size_t)(r0 + 8) * N + col] = L;
            }
        }
    }
}

// -------------- mma.sync bf16x3 flash attention -----------------------------
// CTA: (q-tile 128, head, batch). 8 warps x 16 rows. KV tiles of 128.
#define PDB 144   // padded smem row stride bytes (64 bf16 data + 16B pad)
#define QT  (128 * PDB)          // 18432 B per [128][64] tile
#define KVB (4 * QT)             // K/V hi/lo per buffer

__global__ __launch_bounds__(256)
void attn_mma(const __nv_bfloat16* __restrict__ qh, const __nv_bfloat16* __restrict__ ql,
              __nv_bfloat16* __restrict__ ohi, __nv_bfloat16* __restrict__ olo)
{
    extern __shared__ char smem[];
    const uint32_t sQh = smem_u32(smem);
    const uint32_t sQl = sQh + QT;
    const uint32_t sKV = sQl + QT;    // two buffers of [Kh,Kl,Vh,Vl]

    const int t = threadIdx.x, lane = t & 31, wid = t >> 5;
    const int qt = blockIdx.x, h = blockIdx.y, b = blockIdx.z;
    const int q0 = qt * 128;
    const size_t rowE = 3 * EMBED;
    const __nv_bfloat16* qbh = qh + (size_t)b * SEQ * rowE + h * HEAD_DIM;
    const __nv_bfloat16* qbl = ql + (size_t)b * SEQ * rowE + h * HEAD_DIM;

    const int lr = t >> 1;          // 0..127 row
    const int cb = (t & 1) * 4;     // 4 chunks of 16B per thread -> 128B/row

    // group 0: Q tiles (full 128 B per row)
    #pragma unroll
    for (int cc = 0; cc < 4; cc++) {
        const uint32_t so = lr * PDB + (cb + cc) * 16;
        const size_t go = (size_t)(q0 + lr) * rowE + (cb + cc) * 8;
        cpasync16(sQh + so, qbh + go);
        cpasync16(sQl + so, qbl + go);
    }
    asm volatile("cp.async.commit_group;" ::: "memory");

    auto issueKV = [&](int kt, int buf) {
        const uint32_t sb = sKV + buf * KVB;
        const size_t krow = (size_t)(kt * 128 + lr) * rowE;
        #pragma unroll
        for (int cc = 0; cc < 4; cc++) {
            const uint32_t so = lr * PDB + (cb + cc) * 16;
            const size_t gk = krow + EMBED + (cb + cc) * 8;
            const size_t gv = krow + 2 * EMBED + (cb + cc) * 8;
            cpasync16(sb + 0 * QT + so, qbh + gk);
            cpasync16(sb + 1 * QT + so, qbl + gk);
            cpasync16(sb + 2 * QT + so, qbh + gv);
            cpasync16(sb + 3 * QT + so, qbl + gv);
        }
        asm volatile("cp.async.commit_group;" ::: "memory");
    };

    issueKV(0, 0);

    float o[8][4] = {};
    float m_lo = -1e30f, m_hi = -1e30f, l_lo = 0.0f, l_hi = 0.0f;
    uint32_t qfh[4][4], qfl[4][4];

    const int NKV = SEQ / 128;
    for (int kt = 0; kt < NKV; kt++) {
        if (kt + 1 < NKV) {
            issueKV(kt + 1, (kt + 1) & 1);
            asm volatile("cp.async.wait_group 1;" ::: "memory");
        } else {
            asm volatile("cp.async.wait_group 0;" ::: "memory");
        }
        __syncthreads();

        if (kt == 0) {
            #pragma unroll
            for (int ks = 0; ks < 4; ks++) {
                const uint32_t arow = ((wid * 16) + (lane & 15)) * PDB + ks * 32 + (lane >> 4) * 16;
                ldsm4(qfh[ks], sQh + arow);
                ldsm4(qfl[ks], sQl + arow);
            }
        }

        const uint32_t sb  = sKV + (kt & 1) * KVB;
        const uint32_t aKh = sb, aKl = sb + QT, aVh = sb + 2 * QT, aVl = sb + 3 * QT;

        // ---- S = Q K^T (3-term compensated) ----
        float s[16][4] = {};
        #pragma unroll
        for (int ks = 0; ks < 4; ks++) {
            const uint32_t bbase = (lane & 7) * PDB + ks * 32 + ((lane >> 3) & 1) * 16;
            uint32_t kf[16][2];
            #pragma unroll
            for (int j = 0; j < 16; j++) ldsm2(kf[j], aKh + bbase + j * 8 * PDB);
            #pragma unroll
            for (int j = 0; j < 16; j++) mma16816(s[j], qfh[ks], kf[j]);
            #pragma unroll
            for (int j = 0; j < 16; j++) mma16816(s[j], qfl[ks], kf[j]);
            #pragma unroll
            for (int j = 0; j < 16; j++) ldsm2(kf[j], aKl + bbase + j * 8 * PDB);
            #pragma unroll
            for (int j = 0; j < 16; j++) mma16816(s[j], qfh[ks], kf[j]);
        }

        // ---- online softmax ----
        float tmax_lo = -1e30f, tmax_hi = -1e30f;
        #pragma unroll
        for (int j = 0; j < 16; j++) {
            tmax_lo = fmaxf(tmax_lo, fmaxf(s[j][0], s[j][1]));
            tmax_hi = fmaxf(tmax_hi, fmaxf(s[j][2], s[j][3]));
        }
        tmax_lo = fmaxf(tmax_lo, __shfl_xor_sync(0xffffffffu, tmax_lo, 1));
        tmax_lo = fmaxf(tmax_lo, __shfl_xor_sync(0xffffffffu, tmax_lo, 2));
        tmax_hi = fmaxf(tmax_hi, __shfl_xor_sync(0xffffffffu, tmax_hi, 1));
        tmax_hi = fmaxf(tmax_hi, __shfl_xor_sync(0xffffffffu, tmax_hi, 2));
        float mn_lo = fmaxf(m_lo, tmax_lo), mn_hi = fmaxf(m_hi, tmax_hi);
        float corr_lo = __expf(m_lo - mn_lo), corr_hi = __expf(m_hi - mn_hi);
        m_lo = mn_lo; m_hi = mn_hi;

        float sum_lo = 0.0f, sum_hi = 0.0f;
        #pragma unroll
        for (int j = 0; j < 16; j++) {
            s[j][0] = __expf(s[j][0] - m_lo); s[j][1] = __expf(s[j][1] - m_lo);
            s[j][2] = __expf(s[j][2] - m_hi); s[j][3] = __expf(s[j][3] - m_hi);
            sum_lo += s[j][0] + s[j][1];
            sum_hi += s[j][2] + s[j][3];
        }
        sum_lo += __shfl_xor_sync(0xffffffffu, sum_lo, 1);
        sum_lo += __shfl_xor_sync(0xffffffffu, sum_lo, 2);
        sum_hi += __shfl_xor_sync(0xffffffffu, sum_hi, 1);
        sum_hi += __shfl_xor_sync(0xffffffffu, sum_hi, 2);
        l_lo = l_lo * corr_lo + sum_lo;
        l_hi = l_hi * corr_hi + sum_hi;
        #pragma unroll
        for (int j = 0; j < 8; j++) {
            o[j][0] *= corr_lo; o[j][1] *= corr_lo;
            o[j][2] *= corr_hi; o[j][3] *= corr_hi;
        }

        // ---- O += P V (3-term compensated) ----
        #pragma unroll
        for (int kk = 0; kk < 8; kk++) {
            uint32_t ph[4], pl[4];
            split2(s[2*kk  ][0], s[2*kk  ][1], ph[0], pl[0]);
            split2(s[2*kk  ][2], s[2*kk  ][3], ph[1], pl[1]);
            split2(s[2*kk+1][0], s[2*kk+1][1], ph[2], pl[2]);
            split2(s[2*kk+1][2], s[2*kk+1][3], ph[3], pl[3]);

            const uint32_t vrow = (kk * 16 + (lane & 15)) * PDB;
            uint32_t vf[8][2];
            #pragma unroll
            for (int j = 0; j < 8; j++) ldsm2t(vf[j], aVh + vrow + j * 16);
            #pragma unroll
            for (int j = 0; j < 8; j++) mma16816(o[j], ph, vf[j]);
            #pragma unroll
            for (int j = 0; j < 8; j++) mma16816(o[j], pl, vf[j]);
            #pragma unroll
            for (int j = 0; j < 8; j++) ldsm2t(vf[j], aVl + vrow + j * 16);
            #pragma unroll
            for (int j = 0; j < 8; j++) mma16816(o[j], ph, vf[j]);
        }
        __syncthreads();
    }

    // ---- epilogue: normalize + bf16 hi/lo out ----
    const float inv_lo = 1.0f / l_lo, inv_hi = 1.0f / l_hi;
    const int r_lo = q0 + wid * 16 + (lane >> 2);
    const size_t obase = (size_t)(b * SEQ) * EMBED + (size_t)h * HEAD_DIM;
    #pragma unroll
    for (int j = 0; j < 8; j++) {
        const int col = j * 8 + (lane & 3) * 2;
        uint32_t H, L;
        split2(o[j][0] * inv_lo, o[j][1] * inv_lo, H, L);
        *(uint32_t*)&ohi[obase + (size_t)r_lo * EMBED + col] = H;
        *(uint32_t*)&olo[obase + (size_t)r_lo * EMBED + col] = L;
        split2(o[j][2] * inv_hi, o[j][3] * inv_hi, H, L);
        *(uint32_t*)&ohi[obase + (size_t)(r_lo + 8) * EMBED + col] = H;
        *(uint32_t*)&olo[obase + (size_t)(r_lo + 8) * EMBED + col] = L;
    }
}

// ---------------------------------------------------------------------------
extern "C" void kernel_launch(void* const* d_in, const int* in_sizes, int n_in,
                              void* d_out, int out_size)
{
    const float* x      = (const float*)d_in[0];
    const float* w_qkv  = (const float*)d_in[1];
    const float* b_qkv  = (const float*)d_in[2];
    const float* w_proj = (const float*)d_in[3];
    const float* b_proj = (const float*)d_in[4];
    float* out = (float*)d_out;

    __nv_bfloat16 *xhi, *xlo, *wqh, *wql, *wph, *wpl, *qh, *ql, *ahi, *alo;
    cudaGetSymbolAddress((void**)&xhi, g_xhi);
    cudaGetSymbolAddress((void**)&xlo, g_xlo);
    cudaGetSymbolAddress((void**)&wqh, g_wqh);
    cudaGetSymbolAddress((void**)&wql, g_wql);
    cudaGetSymbolAddress((void**)&wph, g_wph);
    cudaGetSymbolAddress((void**)&wpl, g_wpl);
    cudaGetSymbolAddress((void**)&qh, g_qh);
    cudaGetSymbolAddress((void**)&ql, g_ql);
    cudaGetSymbolAddress((void**)&ahi, g_ahi);
    cudaGetSymbolAddress((void**)&alo, g_alo);

    const int M = MTOT;
    const int smem_gemm = 2 * 4 * TILEB;       // 81920
    const int smem_attn = 2 * QT + 2 * KVB;    // 184320

    cudaFuncSetAttribute(gemm_mma<0>, cudaFuncAttributeMaxDynamicSharedMemorySize, smem_gemm);
    cudaFuncSetAttribute(gemm_mma<1>, cudaFuncAttributeMaxDynamicSharedMemorySize, smem_gemm);
    cudaFuncSetAttribute(attn_mma, cudaFuncAttributeMaxDynamicSharedMemorySize, smem_attn);

    // splits
    {
        int n4 = M * EMBED / 4;
        split_kernel<<<(n4 + 255) / 256, 256>>>(x, xhi, xlo, n4);
        n4 = 3 * EMBED * EMBED / 4;
        split_kernel<<<(n4 + 255) / 256, 256>>>(w_qkv, wqh, wql, n4);
        n4 = EMBED * EMBED / 4;
        split_kernel<<<(n4 + 255) / 256, 256>>>(w_proj, wph, wpl, n4);
    }

    // 1) QKV projection -> bf16 hi/lo (Q pre-scaled by 0.125)
    {
        dim3 g(3 * EMBED / 128, M / 128);
        gemm_mma<1><<<g, 256, smem_gemm>>>(xhi, xlo, wqh, wql, b_qkv,
                                           nullptr, qh, ql, M, 3 * EMBED, EMBED);
    }

    // 2) attention (tensor cores) -> bf16 hi/lo
    {
        dim3 g(SEQ / 128, HEADS, BATCH);
        attn_mma<<<g, 256, smem_attn>>>(qh, ql, ahi, alo);
    }

    // 3) proj GEMM -> fp32 out
    {
        dim3 g(EMBED / 128, M / 128);
        gemm_mma<0><<<g, 256, smem_gemm>>>(ahi, alo, wph, wpl, b_proj,
                                           out, nullptr, nullptr, M, EMBED, EMBED);
    }
}

// round 7
// speedup vs baseline: 3.2231x; 1.3204x over previous
#include <cuda_runtime.h>
#include <cuda.h>
#include <cuda_bf16.h>
#include <cstdint>

#define EMBED    1024
#define HEADS    16
#define HEAD_DIM 64
#define SEQ      2048
#define BATCH    2
#define MTOT     (BATCH * SEQ)    // 4096

// ------------------------------ scratch (TMA needs alignment) ---------------
__device__ __align__(1024) __nv_bfloat16 g_xhi[(size_t)MTOT * EMBED];
__device__ __align__(1024) __nv_bfloat16 g_xlo[(size_t)MTOT * EMBED];
__device__ __align__(1024) __nv_bfloat16 g_wqh[(size_t)3 * EMBED * EMBED];
__device__ __align__(1024) __nv_bfloat16 g_wql[(size_t)3 * EMBED * EMBED];
__device__ __align__(1024) __nv_bfloat16 g_wph[(size_t)EMBED * EMBED];
__device__ __align__(1024) __nv_bfloat16 g_wpl[(size_t)EMBED * EMBED];
__device__ __align__(1024) __nv_bfloat16 g_qh[(size_t)MTOT * 3 * EMBED];
__device__ __align__(1024) __nv_bfloat16 g_ql[(size_t)MTOT * 3 * EMBED];
__device__ __align__(1024) __nv_bfloat16 g_ahi[(size_t)MTOT * EMBED];
__device__ __align__(1024) __nv_bfloat16 g_alo[(size_t)MTOT * EMBED];

// --------------------------- PTX helpers ------------------------------------
__device__ __forceinline__ uint32_t smem_u32(const void* p) {
    uint32_t a;
    asm("{ .reg .u64 t; cvta.to.shared.u64 t, %1; cvt.u32.u64 %0, t; }" : "=r"(a) : "l"(p));
    return a;
}
__device__ __forceinline__ void ldsm4(uint32_t* a, uint32_t addr) {
    asm volatile("ldmatrix.sync.aligned.m8n8.x4.shared.b16 {%0,%1,%2,%3}, [%4];"
                 : "=r"(a[0]), "=r"(a[1]), "=r"(a[2]), "=r"(a[3]) : "r"(addr));
}
__device__ __forceinline__ void ldsm2(uint32_t* b, uint32_t addr) {
    asm volatile("ldmatrix.sync.aligned.m8n8.x2.shared.b16 {%0,%1}, [%2];"
                 : "=r"(b[0]), "=r"(b[1]) : "r"(addr));
}
__device__ __forceinline__ void ldsm2t(uint32_t* b, uint32_t addr) {
    asm volatile("ldmatrix.sync.aligned.m8n8.x2.trans.shared.b16 {%0,%1}, [%2];"
                 : "=r"(b[0]), "=r"(b[1]) : "r"(addr));
}
__device__ __forceinline__ void mma16816(float* c, const uint32_t* a, const uint32_t* b) {
    asm volatile(
        "mma.sync.aligned.m16n8k16.row.col.f32.bf16.bf16.f32 "
        "{%0,%1,%2,%3},{%4,%5,%6,%7},{%8,%9},{%0,%1,%2,%3};"
        : "+f"(c[0]), "+f"(c[1]), "+f"(c[2]), "+f"(c[3])
        : "r"(a[0]), "r"(a[1]), "r"(a[2]), "r"(a[3]), "r"(b[0]), "r"(b[1]));
}
__device__ __forceinline__ void tma2d(uint32_t s, const CUtensorMap* m, int x, int y, uint32_t mb) {
    asm volatile(
        "cp.async.bulk.tensor.2d.shared::cta.global.tile.mbarrier::complete_tx::bytes "
        "[%0], [%1, {%2, %3}], [%4];"
        :: "r"(s), "l"(m), "r"(x), "r"(y), "r"(mb) : "memory");
}
__device__ __forceinline__ void mb_init(uint32_t mb, uint32_t cnt) {
    asm volatile("mbarrier.init.shared.b64 [%0], %1;" :: "r"(mb), "r"(cnt) : "memory");
}
__device__ __forceinline__ void mb_expect(uint32_t mb, uint32_t bytes) {
    asm volatile("mbarrier.arrive.expect_tx.shared.b64 _, [%0], %1;" :: "r"(mb), "r"(bytes) : "memory");
}
#define MBWAIT(mb, ph)                                                          \
    asm volatile("{\n .reg .pred p;\nWL%=:\n"                                   \
                 " mbarrier.try_wait.parity.shared.b64 p, [%0], %1;\n"          \
                 " @!p bra WL%=;\n}"                                            \
                 :: "r"(mb), "r"((uint32_t)(ph)) : "memory")

__device__ __forceinline__ uint32_t pack2(float a, float b) {
    __nv_bfloat162 t = __floats2bfloat162_rn(a, b);
    return *(uint32_t*)&t;
}
__device__ __forceinline__ void split2(float a, float b, uint32_t& H, uint32_t& L) {
    __nv_bfloat16 ha = __float2bfloat16(a), hb = __float2bfloat16(b);
    float la = a - __bfloat162float(ha), lb = b - __bfloat162float(hb);
    H = ((uint32_t)__bfloat16_as_ushort(hb) << 16) | __bfloat16_as_ushort(ha);
    L = pack2(la, lb);
}

// -------------------- fp32 -> (bf16 hi, bf16 lo) split ----------------------
__global__ __launch_bounds__(256)
void split_kernel(const float* __restrict__ in, __nv_bfloat16* __restrict__ hi,
                  __nv_bfloat16* __restrict__ lo, int n4)
{
    int i = blockIdx.x * blockDim.x + threadIdx.x;
    if (i >= n4) return;
    float4 v = ((const float4*)in)[i];
    uint2 H, L;
    split2(v.x, v.y, H.x, L.x);
    split2(v.z, v.w, H.y, L.y);
    ((uint2*)hi)[i] = H;
    ((uint2*)lo)[i] = L;
}

// ----------- TMA + mma.sync bf16x3 GEMM: C = A W^T + bias -------------------
// BK=64, 3-stage TMA pipeline, SW128 swizzled smem, 8 warps (warp tile 64x32).
#define GSTG 65536                       // 4 tiles x 16KB per stage
#define GSM  (1024 + 3 * GSTG)

template<int MODE>
__global__ __launch_bounds__(256)
void gemm_tma(const __grid_constant__ CUtensorMap mAh,
              const __grid_constant__ CUtensorMap mAl,
              const __grid_constant__ CUtensorMap mBh,
              const __grid_constant__ CUtensorMap mBl,
              const float* __restrict__ bias, float* __restrict__ C,
              __nv_bfloat16* __restrict__ Chi, __nv_bfloat16* __restrict__ Clo,
              int M, int N, int K)
{
    extern __shared__ char smem[];
    __shared__ uint64_t mbar[3];
    const uint32_t sb0 = (smem_u32(smem) + 1023) & ~1023u;

    const int t = threadIdx.x, lane = t & 31, wid = t >> 5;
    const int row0 = blockIdx.y * 128, col0 = blockIdx.x * 128;
    const int m0 = (wid >> 2) * 64, n0 = (wid & 3) * 32;

    uint32_t mb[3];
    #pragma unroll
    for (int s = 0; s < 3; s++) mb[s] = smem_u32(&mbar[s]);
    if (t == 0) {
        #pragma unroll
        for (int s = 0; s < 3; s++) mb_init(mb[s], 1);
    }
    __syncthreads();

    auto issue = [&](int kt) {
        const int s = kt % 3;
        const uint32_t base = sb0 + s * GSTG;
        mb_expect(mb[s], GSTG);
        tma2d(base,         &mAh, kt * 64, row0, mb[s]);
        tma2d(base + 16384, &mAl, kt * 64, row0, mb[s]);
        tma2d(base + 32768, &mBh, kt * 64, col0, mb[s]);
        tma2d(base + 49152, &mBl, kt * 64, col0, mb[s]);
    };
    if (t == 0) { issue(0); issue(1); }

    float c[4][4][4] = {};
    const int KT = K / 64;

    for (int kt = 0; kt < KT; kt++) {
        if (t == 0 && kt + 2 < KT) issue(kt + 2);
        const int s = kt % 3;
        MBWAIT(mb[s], (kt / 3) & 1);
        const uint32_t base = sb0 + s * GSTG;
        const uint32_t aAh = base, aAl = base + 16384, aBh = base + 32768, aBl = base + 49152;

        #pragma unroll
        for (int ks = 0; ks < 4; ks++) {
            uint32_t ad[4], bd[4];
            #pragma unroll
            for (int i = 0; i < 4; i++) {
                const int r = m0 + (lane & 15) + i * 16;
                const int ch = 2 * ks + (lane >> 4);
                ad[i] = (uint32_t)(r * 128 + ((ch ^ (r & 7)) << 4));
            }
            #pragma unroll
            for (int j = 0; j < 4; j++) {
                const int r = n0 + (lane & 7) + j * 8;
                const int ch = 2 * ks + ((lane >> 3) & 1);
                bd[j] = (uint32_t)(r * 128 + ((ch ^ (r & 7)) << 4));
            }
            uint32_t ah[4][4], al[4][4], bh[4][2], bl[4][2];
            #pragma unroll
            for (int i = 0; i < 4; i++) ldsm4(ah[i], aAh + ad[i]);
            #pragma unroll
            for (int j = 0; j < 4; j++) ldsm2(bh[j], aBh + bd[j]);
            #pragma unroll
            for (int i = 0; i < 4; i++)
                #pragma unroll
                for (int j = 0; j < 4; j++) mma16816(c[i][j], ah[i], bh[j]);
            #pragma unroll
            for (int j = 0; j < 4; j++) ldsm2(bl[j], aBl + bd[j]);
            #pragma unroll
            for (int i = 0; i < 4; i++)
                #pragma unroll
                for (int j = 0; j < 4; j++) mma16816(c[i][j], ah[i], bl[j]);
            #pragma unroll
            for (int i = 0; i < 4; i++) ldsm4(al[i], aAl + ad[i]);
            #pragma unroll
            for (int i = 0; i < 4; i++)
                #pragma unroll
                for (int j = 0; j < 4; j++) mma16816(c[i][j], al[i], bh[j]);
        }
        __syncthreads();
    }

    #pragma unroll
    for (int j = 0; j < 4; j++) {
        const int col = col0 + n0 + j * 8 + (lane & 3) * 2;
        const float2 bb = *(const float2*)&bias[col];
        const float sc = (MODE == 1 && col < EMBED) ? 0.125f : 1.0f;
        #pragma unroll
        for (int i = 0; i < 4; i++) {
            const int r0 = row0 + m0 + i * 16 + (lane >> 2);
            float v0 = (c[i][j][0] + bb.x) * sc, v1 = (c[i][j][1] + bb.y) * sc;
            float v2 = (c[i][j][2] + bb.x) * sc, v3 = (c[i][j][3] + bb.y) * sc;
            if (MODE == 0) {
                *(float2*)&C[(size_t)r0 * N + col]       = make_float2(v0, v1);
                *(float2*)&C[(size_t)(r0 + 8) * N + col] = make_float2(v2, v3);
            } else {
                uint32_t H, L;
                split2(v0, v1, H, L);
                *(uint32_t*)&Chi[(size_t)r0 * N + col] = H;
                *(uint32_t*)&Clo[(size_t)r0 * N + col] = L;
                split2(v2, v3, H, L);
                *(uint32_t*)&Chi[(size_t)(r0 + 8) * N + col] = H;
                *(uint32_t*)&Clo[(size_t)(r0 + 8) * N + col] = L;
            }
        }
    }
}

// -------------- TMA + mma.sync bf16x3 flash attention -----------------------
// CTA: (q-tile 128, head, batch). Q 2x16KB + 2-stage KV ring (4x16KB each).
#define ASTG 65536
#define ASM_BYTES (1024 + 2 * 16384 + 2 * ASTG)

__global__ __launch_bounds__(256)
void attn_tma(const __grid_constant__ CUtensorMap mQh,
              const __grid_constant__ CUtensorMap mQl,
              __nv_bfloat16* __restrict__ ohi, __nv_bfloat16* __restrict__ olo)
{
    extern __shared__ char smem[];
    __shared__ uint64_t mbar[3];   // [0]=Q, [1..2]=KV stages
    const uint32_t sb0 = (smem_u32(smem) + 1023) & ~1023u;
    const uint32_t sQh = sb0, sQl = sb0 + 16384;
    const uint32_t sKV = sb0 + 32768;

    const int t = threadIdx.x, lane = t & 31, wid = t >> 5;
    const int qt = blockIdx.x, h = blockIdx.y, b = blockIdx.z;
    const int qrow = b * SEQ + qt * 128;

    uint32_t qb = smem_u32(&mbar[0]);
    uint32_t kb[2] = { smem_u32(&mbar[1]), smem_u32(&mbar[2]) };
    if (t == 0) { mb_init(qb, 1); mb_init(kb[0], 1); mb_init(kb[1], 1); }
    __syncthreads();

    auto issueKV = [&](int kt) {
        const int s = kt & 1;
        const uint32_t base = sKV + s * ASTG;
        const int krow = b * SEQ + kt * 128;
        mb_expect(kb[s], ASTG);
        tma2d(base,         &mQh, EMBED + h * HEAD_DIM,     krow, kb[s]);   // K hi
        tma2d(base + 16384, &mQl, EMBED + h * HEAD_DIM,     krow, kb[s]);   // K lo
        tma2d(base + 32768, &mQh, 2 * EMBED + h * HEAD_DIM, krow, kb[s]);   // V hi
        tma2d(base + 49152, &mQl, 2 * EMBED + h * HEAD_DIM, krow, kb[s]);   // V lo
    };
    if (t == 0) {
        mb_expect(qb, 32768);
        tma2d(sQh, &mQh, h * HEAD_DIM, qrow, qb);
        tma2d(sQl, &mQl, h * HEAD_DIM, qrow, qb);
        issueKV(0);
        issueKV(1);
    }

    // Q fragments (swizzled)
    uint32_t qfh[4][4], qfl[4][4];
    MBWAIT(qb, 0);
    #pragma unroll
    for (int ks = 0; ks < 4; ks++) {
        const int r = wid * 16 + (lane & 15);
        const int ch = 2 * ks + (lane >> 4);
        const uint32_t qd = (uint32_t)(r * 128 + ((ch ^ (r & 7)) << 4));
        ldsm4(qfh[ks], sQh + qd);
        ldsm4(qfl[ks], sQl + qd);
    }

    float o[8][4] = {};
    float m_lo = -1e30f, m_hi = -1e30f, l_lo = 0.0f, l_hi = 0.0f;

    const int NKV = SEQ / 128;
    for (int kt = 0; kt < NKV; kt++) {
        const int s = kt & 1;
        MBWAIT(kb[s], (kt / 2) & 1);
        const uint32_t base = sKV + s * ASTG;
        const uint32_t aKh = base, aKl = base + 16384, aVh = base + 32768, aVl = base + 49152;

        // ---- S = Q K^T (3-term compensated) ----
        float sfr[16][4] = {};
        #pragma unroll
        for (int ks = 0; ks < 4; ks++) {
            uint32_t kd[16];
            #pragma unroll
            for (int j = 0; j < 16; j++) {
                const int r = j * 8 + (lane & 7);
                const int ch = 2 * ks + ((lane >> 3) & 1);
                kd[j] = (uint32_t)(r * 128 + ((ch ^ (r & 7)) << 4));
            }
            uint32_t kf[16][2];
            #pragma unroll
            for (int j = 0; j < 16; j++) ldsm2(kf[j], aKh + kd[j]);
            #pragma unroll
            for (int j = 0; j < 16; j++) mma16816(sfr[j], qfh[ks], kf[j]);
            #pragma unroll
            for (int j = 0; j < 16; j++) mma16816(sfr[j], qfl[ks], kf[j]);
            #pragma unroll
            for (int j = 0; j < 16; j++) ldsm2(kf[j], aKl + kd[j]);
            #pragma unroll
            for (int j = 0; j < 16; j++) mma16816(sfr[j], qfh[ks], kf[j]);
        }

        // ---- online softmax ----
        float tmax_lo = -1e30f, tmax_hi = -1e30f;
        #pragma unroll
        for (int j = 0; j < 16; j++) {
            tmax_lo = fmaxf(tmax_lo, fmaxf(sfr[j][0], sfr[j][1]));
            tmax_hi = fmaxf(tmax_hi, fmaxf(sfr[j][2], sfr[j][3]));
        }
        tmax_lo = fmaxf(tmax_lo, __shfl_xor_sync(0xffffffffu, tmax_lo, 1));
        tmax_lo = fmaxf(tmax_lo, __shfl_xor_sync(0xffffffffu, tmax_lo, 2));
        tmax_hi = fmaxf(tmax_hi, __shfl_xor_sync(0xffffffffu, tmax_hi, 1));
        tmax_hi = fmaxf(tmax_hi, __shfl_xor_sync(0xffffffffu, tmax_hi, 2));
        float mn_lo = fmaxf(m_lo, tmax_lo), mn_hi = fmaxf(m_hi, tmax_hi);
        float corr_lo = __expf(m_lo - mn_lo), corr_hi = __expf(m_hi - mn_hi);
        m_lo = mn_lo; m_hi = mn_hi;

        float sum_lo = 0.0f, sum_hi = 0.0f;
        #pragma unroll
        for (int j = 0; j < 16; j++) {
            sfr[j][0] = __expf(sfr[j][0] - m_lo); sfr[j][1] = __expf(sfr[j][1] - m_lo);
            sfr[j][2] = __expf(sfr[j][2] - m_hi); sfr[j][3] = __expf(sfr[j][3] - m_hi);
            sum_lo += sfr[j][0] + sfr[j][1];
            sum_hi += sfr[j][2] + sfr[j][3];
        }
        sum_lo += __shfl_xor_sync(0xffffffffu, sum_lo, 1);
        sum_lo += __shfl_xor_sync(0xffffffffu, sum_lo, 2);
        sum_hi += __shfl_xor_sync(0xffffffffu, sum_hi, 1);
        sum_hi += __shfl_xor_sync(0xffffffffu, sum_hi, 2);
        l_lo = l_lo * corr_lo + sum_lo;
        l_hi = l_hi * corr_hi + sum_hi;
        #pragma unroll
        for (int j = 0; j < 8; j++) {
            o[j][0] *= corr_lo; o[j][1] *= corr_lo;
            o[j][2] *= corr_hi; o[j][3] *= corr_hi;
        }

        // ---- O += P V (3-term compensated) ----
        #pragma unroll
        for (int kk = 0; kk < 8; kk++) {
            uint32_t ph[4], pl[4];
            split2(sfr[2*kk  ][0], sfr[2*kk  ][1], ph[0], pl[0]);
            split2(sfr[2*kk  ][2], sfr[2*kk  ][3], ph[1], pl[1]);
            split2(sfr[2*kk+1][0], sfr[2*kk+1][1], ph[2], pl[2]);
            split2(sfr[2*kk+1][2], sfr[2*kk+1][3], ph[3], pl[3]);

            const int r = kk * 16 + (lane & 15);
            uint32_t vf[8][2];
            #pragma unroll
            for (int j = 0; j < 8; j++)
                ldsm2t(vf[j], aVh + (uint32_t)(r * 128 + ((j ^ (r & 7)) << 4)));
            #pragma unroll
            for (int j = 0; j < 8; j++) mma16816(o[j], ph, vf[j]);
            #pragma unroll
            for (int j = 0; j < 8; j++) mma16816(o[j], pl, vf[j]);
            #pragma unroll
            for (int j = 0; j < 8; j++)
                ldsm2t(vf[j], aVl + (uint32_t)(r * 128 + ((j ^ (r & 7)) << 4)));
            #pragma unroll
            for (int j = 0; j < 8; j++) mma16816(o[j], ph, vf[j]);
        }
        __syncthreads();
        if (t == 0 && kt + 2 < NKV) issueKV(kt + 2);
    }

    // ---- epilogue: normalize + bf16 hi/lo out ----
    const float inv_lo = 1.0f / l_lo, inv_hi = 1.0f / l_hi;
    const int r_lo = qt * 128 + wid * 16 + (lane >> 2);
    const size_t obase = (size_t)(b * SEQ) * EMBED + (size_t)h * HEAD_DIM;
    #pragma unroll
    for (int j = 0; j < 8; j++) {
        const int col = j * 8 + (lane & 3) * 2;
        uint32_t H, L;
        split2(o[j][0] * inv_lo, o[j][1] * inv_lo, H, L);
        *(uint32_t*)&ohi[obase + (size_t)r_lo * EMBED + col] = H;
        *(uint32_t*)&olo[obase + (size_t)r_lo * EMBED + col] = L;
        split2(o[j][2] * inv_hi, o[j][3] * inv_hi, H, L);
        *(uint32_t*)&ohi[obase + (size_t)(r_lo + 8) * EMBED + col] = H;
        *(uint32_t*)&olo[obase + (size_t)(r_lo + 8) * EMBED + col] = L;
    }
}

// ---------------------------------------------------------------------------
typedef CUresult (CUDAAPI *tmap_fn_t)(CUtensorMap*, CUtensorMapDataType, cuuint32_t,
    void*, const cuuint64_t*, const cuuint64_t*, const cuuint32_t*, const cuuint32_t*,
    CUtensorMapInterleave, CUtensorMapSwizzle, CUtensorMapL2promotion, CUtensorMapFloatOOBfill);

static void make_map(CUtensorMap* m, tmap_fn_t fn, void* base,
                     uint64_t cols, uint64_t rows)
{
    cuuint64_t dims[2]    = { cols, rows };
    cuuint64_t strides[1] = { cols * 2 };
    cuuint32_t box[2]     = { 64, 128 };
    cuuint32_t es[2]      = { 1, 1 };
    fn(m, CU_TENSOR_MAP_DATA_TYPE_BFLOAT16, 2, base, dims, strides, box, es,
       CU_TENSOR_MAP_INTERLEAVE_NONE, CU_TENSOR_MAP_SWIZZLE_128B,
       CU_TENSOR_MAP_L2_PROMOTION_L2_128B, CU_TENSOR_MAP_FLOAT_OOB_FILL_NONE);
}

extern "C" void kernel_launch(void* const* d_in, const int* in_sizes, int n_in,
                              void* d_out, int out_size)
{
    const float* x      = (const float*)d_in[0];
    const float* w_qkv  = (const float*)d_in[1];
    const float* b_qkv  = (const float*)d_in[2];
    const float* w_proj = (const float*)d_in[3];
    const float* b_proj = (const float*)d_in[4];
    float* out = (float*)d_out;

    __nv_bfloat16 *xhi, *xlo, *wqh, *wql, *wph, *wpl, *qh, *ql, *ahi, *alo;
    cudaGetSymbolAddress((void**)&xhi, g_xhi);
    cudaGetSymbolAddress((void**)&xlo, g_xlo);
    cudaGetSymbolAddress((void**)&wqh, g_wqh);
    cudaGetSymbolAddress((void**)&wql, g_wql);
    cudaGetSymbolAddress((void**)&wph, g_wph);
    cudaGetSymbolAddress((void**)&wpl, g_wpl);
    cudaGetSymbolAddress((void**)&qh, g_qh);
    cudaGetSymbolAddress((void**)&ql, g_ql);
    cudaGetSymbolAddress((void**)&ahi, g_ahi);
    cudaGetSymbolAddress((void**)&alo, g_alo);

    tmap_fn_t fn = nullptr;
    cudaDriverEntryPointQueryResult qres;
    cudaGetDriverEntryPoint("cuTensorMapEncodeTiled", (void**)&fn,
                            cudaEnableDefault, &qres);

    static CUtensorMap mXh, mXl, mWqh, mWql, mWph, mWpl, mQh, mQl, mAh, mAl;
    make_map(&mXh,  fn, xhi, EMBED,     MTOT);
    make_map(&mXl,  fn, xlo, EMBED,     MTOT);
    make_map(&mWqh, fn, wqh, EMBED,     3 * EMBED);
    make_map(&mWql, fn, wql, EMBED,     3 * EMBED);
    make_map(&mWph, fn, wph, EMBED,     EMBED);
    make_map(&mWpl, fn, wpl, EMBED,     EMBED);
    make_map(&mQh,  fn, qh,  3 * EMBED, MTOT);
    make_map(&mQl,  fn, ql,  3 * EMBED, MTOT);
    make_map(&mAh,  fn, ahi, EMBED,     MTOT);
    make_map(&mAl,  fn, alo, EMBED,     MTOT);

    const int M = MTOT;
    cudaFuncSetAttribute(gemm_tma<0>, cudaFuncAttributeMaxDynamicSharedMemorySize, GSM);
    cudaFuncSetAttribute(gemm_tma<1>, cudaFuncAttributeMaxDynamicSharedMemorySize, GSM);
    cudaFuncSetAttribute(attn_tma,    cudaFuncAttributeMaxDynamicSharedMemorySize, ASM_BYTES);

    // splits
    {
        int n4 = M * EMBED / 4;
        split_kernel<<<(n4 + 255) / 256, 256>>>(x, xhi, xlo, n4);
        n4 = 3 * EMBED * EMBED / 4;
        split_kernel<<<(n4 + 255) / 256, 256>>>(w_qkv, wqh, wql, n4);
        n4 = EMBED * EMBED / 4;
        split_kernel<<<(n4 + 255) / 256, 256>>>(w_proj, wph, wpl, n4);
    }

    // 1) QKV projection -> bf16 hi/lo (Q pre-scaled by 0.125)
    {
        dim3 g(3 * EMBED / 128, M / 128);
        gemm_tma<1><<<g, 256, GSM>>>(mXh, mXl, mWqh, mWql, b_qkv,
                                     nullptr, qh, ql, M, 3 * EMBED, EMBED);
    }

    // 2) attention (TMA + tensor cores) -> bf16 hi/lo
    {
        dim3 g(SEQ / 128, HEADS, BATCH);
        attn_tma<<<g, 256, ASM_BYTES>>>(mQh, mQl, ahi, alo);
    }

    // 3) proj GEMM -> fp32 out
    {
        dim3 g(EMBED / 128, M / 128);
        gemm_tma<0><<<g, 256, GSM>>>(mAh, mAl, mWph, mWpl, b_proj,
                                     out, nullptr, nullptr, M, EMBED, EMBED);
    }
}